// round 1
// baseline (speedup 1.0000x reference)
#include <cuda_runtime.h>
#include <math.h>

#define B 2
#define L 2048
#define HID 2048
#define NH 16
#define NKV 4
#define HDIM 128
#define LAT 512
#define SCALE 0.08838834764831845f  /* 1/sqrt(128) */

// ---------------- scratch buffers (no allocations allowed) ----------------
__device__ float g_Q[(size_t)B * L * NH * HDIM];   // 33.5 MB
__device__ float g_C[(size_t)B * L * LAT];         //  8.4 MB
__device__ float g_K[(size_t)B * L * NKV * HDIM];  //  8.4 MB
__device__ float g_V[(size_t)B * L * NKV * HDIM];  //  8.4 MB
__device__ float g_Y[(size_t)B * L * NH * HDIM];   // 33.5 MB

// ---------------- classic 128x128x8 register-tiled SGEMM ----------------
// C[M,N] = A[M,K] @ Bm[K,N], all row-major. Requires M%128==0, N%128==0, K%8==0.
__global__ __launch_bounds__(256) void sgemm_kernel(
    const float* __restrict__ A, const float* __restrict__ Bm,
    float* __restrict__ C, int M, int N, int K) {
  __shared__ float As[8][128];  // transposed A tile
  __shared__ float Bs[8][128];

  const int tid = threadIdx.x;
  const int bx = blockIdx.x, by = blockIdx.y;
  const int tx = tid & 15, ty = tid >> 4;

  const int aRow = tid >> 1;          // 0..127
  const int aCol = (tid & 1) * 4;     // 0 or 4
  const int bRow = tid >> 5;          // 0..7
  const int bCol = (tid & 31) * 4;    // 0..124

  const float* Ab = A + (size_t)by * 128 * K;
  const float* Bb = Bm + (size_t)bx * 128;

  float acc[8][8];
#pragma unroll
  for (int i = 0; i < 8; i++)
#pragma unroll
    for (int j = 0; j < 8; j++) acc[i][j] = 0.f;

  for (int k0 = 0; k0 < K; k0 += 8) {
    float4 a4 = *(const float4*)(Ab + (size_t)aRow * K + k0 + aCol);
    As[aCol + 0][aRow] = a4.x;
    As[aCol + 1][aRow] = a4.y;
    As[aCol + 2][aRow] = a4.z;
    As[aCol + 3][aRow] = a4.w;
    float4 b4 = *(const float4*)(Bb + (size_t)(k0 + bRow) * N + bCol);
    *(float4*)&Bs[bRow][bCol] = b4;
    __syncthreads();

#pragma unroll
    for (int kk = 0; kk < 8; kk++) {
      float ar[8], br[8];
      *(float4*)&ar[0] = *(const float4*)&As[kk][ty * 8];
      *(float4*)&ar[4] = *(const float4*)&As[kk][ty * 8 + 4];
      *(float4*)&br[0] = *(const float4*)&Bs[kk][tx * 8];
      *(float4*)&br[4] = *(const float4*)&Bs[kk][tx * 8 + 4];
#pragma unroll
      for (int i = 0; i < 8; i++)
#pragma unroll
        for (int j = 0; j < 8; j++) acc[i][j] += ar[i] * br[j];
    }
    __syncthreads();
  }

#pragma unroll
  for (int i = 0; i < 8; i++) {
    const size_t row = (size_t)by * 128 + ty * 8 + i;
#pragma unroll
    for (int j = 0; j < 8; j += 4) {
      const int col = bx * 128 + tx * 8 + j;
      float4 v = make_float4(acc[i][j], acc[i][j + 1], acc[i][j + 2], acc[i][j + 3]);
      *(float4*)(C + row * N + col) = v;
    }
  }
}

// ---------------- RoPE (in place), t layout [B, L, H, 128] ----------------
__global__ void rope_kernel(float* __restrict__ t, int H, int total) {
  int i = blockIdx.x * blockDim.x + threadIdx.x;
  if (i >= total) return;
  const int hf = i & 63;           // half-dim index 0..63
  const int h = (i >> 6) % H;
  const int bl = i / (64 * H);
  const int l = bl & (L - 1);
  // inv_freq = 10000^(-hf/64) = exp(-hf * ln(10000)/64)
  const double inv = exp(-(double)hf * 0.14391156831212788);
  const double fr = (double)l * inv;
  const float c = (float)cos(fr);
  const float s = (float)sin(fr);
  float* p = t + ((size_t)bl * H + h) * HDIM;
  const float a = p[hf];
  const float b2 = p[hf + 64];
  p[hf] = a * c - b2 * s;
  p[hf + 64] = b2 * c + a * s;
}

// ---------------- flash attention, fp32, causal + key mask ----------------
// grid (L/64, NH, B), 256 threads (8 warps), warp owns 8 query rows.
// Q layout [B,L,NH,128]; K,V layout [B,L,NKV,128]; Y layout [B,L,NH*128].
__global__ __launch_bounds__(256) void attn_kernel(
    const float* __restrict__ Q, const float* __restrict__ K,
    const float* __restrict__ V, const int* __restrict__ mask,
    float* __restrict__ Y) {
  extern __shared__ float sm[];
  float* Qs = sm;                 // 64*128 (linear)
  float* Ks = sm + 64 * 128;      // 32*128 (XOR-swizzled float4 chunks)
  float* Vs = Ks + 32 * 128;      // 32*128 (XOR-swizzled float4 chunks)
  float* Ps = Vs + 32 * 128;      // 64*33

  const int qt = blockIdx.x, h = blockIdx.y, b = blockIdx.z;
  const int hkv = h >> 2;  // Q_PER_KV = 4
  const int tid = threadIdx.x, warp = tid >> 5, lane = tid & 31;
  const int q0 = qt * 64;
  const int rbase = warp * 8;

  // load Q tile
  for (int i = tid; i < 64 * 32; i += 256) {
    const int r = i >> 5, d4 = i & 31;
    *(float4*)&Qs[r * 128 + d4 * 4] =
        *(const float4*)&Q[((((size_t)b * L + q0 + r) * NH + h) << 7) + d4 * 4];
  }

  float m[8], lsum[8], acc[8][4];
#pragma unroll
  for (int r = 0; r < 8; r++) {
    m[r] = -1e30f;
    lsum[r] = 0.f;
#pragma unroll
    for (int k = 0; k < 4; k++) acc[r][k] = 0.f;
  }

  const int nkt = qt * 2 + 2;  // key tiles of 32 covering [0, q0+64)
  for (int kt = 0; kt < nkt; kt++) {
    const int k0 = kt * 32;
    __syncthreads();  // previous tile fully consumed (and Q visible on iter 0)
    for (int i = tid; i < 32 * 32; i += 256) {
      const int r = i >> 5, d4 = i & 31;
      const size_t g = ((((size_t)b * L + k0 + r) * NKV + hkv) << 7) + d4 * 4;
      const int p = (d4 ^ r) << 2;  // XOR swizzle on 16B chunks
      *(float4*)&Ks[r * 128 + p] = *(const float4*)&K[g];
      *(float4*)&Vs[r * 128 + p] = *(const float4*)&V[g];
    }
    __syncthreads();

    // S[r][lane] = Q[rbase+r] . K[lane]
    float s[8];
#pragma unroll
    for (int r = 0; r < 8; r++) s[r] = 0.f;
    for (int d4 = 0; d4 < 32; d4++) {
      const float4 kv = *(const float4*)&Ks[lane * 128 + ((d4 ^ lane) << 2)];
#pragma unroll
      for (int r = 0; r < 8; r++) {
        const float4 qv = *(const float4*)&Qs[(rbase + r) * 128 + (d4 << 2)];
        s[r] += qv.x * kv.x + qv.y * kv.y + qv.z * kv.z + qv.w * kv.w;
      }
    }

    const int kj = k0 + lane;
    const bool valid_k = (mask[b * L + kj] > 0);
#pragma unroll
    for (int r = 0; r < 8; r++) {
      const int qi = q0 + rbase + r;
      const bool valid = valid_k && (kj <= qi);
      const float sv = valid ? s[r] * SCALE : -1e30f;
      float rm = sv;
#pragma unroll
      for (int off = 16; off > 0; off >>= 1)
        rm = fmaxf(rm, __shfl_xor_sync(0xffffffffu, rm, off));
      const float mnew = fmaxf(m[r], rm);
      const float p = valid ? expf(sv - mnew) : 0.f;
      const float alpha = expf(m[r] - mnew);
      float rs = p;
#pragma unroll
      for (int off = 16; off > 0; off >>= 1)
        rs += __shfl_xor_sync(0xffffffffu, rs, off);
      lsum[r] = lsum[r] * alpha + rs;
      m[r] = mnew;
#pragma unroll
      for (int k = 0; k < 4; k++) acc[r][k] *= alpha;
      Ps[(rbase + r) * 33 + lane] = p;
    }
    __syncwarp();

    // O += P @ V  (lane owns d = lane, lane+32, lane+64, lane+96)
    const int l4 = lane >> 2, lm = lane & 3;
    for (int c = 0; c < 32; c++) {
      const float v0 = Vs[c * 128 + (((l4 + 0) ^ c) << 2) + lm];
      const float v1 = Vs[c * 128 + (((l4 + 8) ^ c) << 2) + lm];
      const float v2 = Vs[c * 128 + (((l4 + 16) ^ c) << 2) + lm];
      const float v3 = Vs[c * 128 + (((l4 + 24) ^ c) << 2) + lm];
#pragma unroll
      for (int r = 0; r < 8; r++) {
        const float p = Ps[(rbase + r) * 33 + c];
        acc[r][0] += p * v0;
        acc[r][1] += p * v1;
        acc[r][2] += p * v2;
        acc[r][3] += p * v3;
      }
    }
  }

  // normalize + write Y[b][q][h*128 + d]
#pragma unroll
  for (int r = 0; r < 8; r++) {
    const float inv = 1.0f / lsum[r];
    const size_t base = ((size_t)b * L + q0 + rbase + r) * (NH * HDIM) + h * HDIM;
    Y[base + lane] = acc[r][0] * inv;
    Y[base + lane + 32] = acc[r][1] * inv;
    Y[base + lane + 64] = acc[r][2] * inv;
    Y[base + lane + 96] = acc[r][3] * inv;
  }
}

// ---------------- launch ----------------
extern "C" void kernel_launch(void* const* d_in, const int* in_sizes, int n_in,
                              void* d_out, int out_size) {
  const float* x = (const float*)d_in[0];
  const float* Wq = (const float*)d_in[1];
  const float* Wc = (const float*)d_in[2];
  const float* Wk = (const float*)d_in[3];
  const float* Wv = (const float*)d_in[4];
  const float* Wo = (const float*)d_in[5];
  const int* mask = (const int*)d_in[6];
  float* out = (float*)d_out;

  float *Qp, *Cp, *Kp, *Vp, *Yp;
  cudaGetSymbolAddress((void**)&Qp, g_Q);
  cudaGetSymbolAddress((void**)&Cp, g_C);
  cudaGetSymbolAddress((void**)&Kp, g_K);
  cudaGetSymbolAddress((void**)&Vp, g_V);
  cudaGetSymbolAddress((void**)&Yp, g_Y);

  const int M = B * L;  // 4096

  // projections
  sgemm_kernel<<<dim3((NH * HDIM) / 128, M / 128), 256>>>(x, Wq, Qp, M, NH * HDIM, HID);
  sgemm_kernel<<<dim3(LAT / 128, M / 128), 256>>>(x, Wc, Cp, M, LAT, HID);
  sgemm_kernel<<<dim3((NKV * HDIM) / 128, M / 128), 256>>>(Cp, Wk, Kp, M, NKV * HDIM, LAT);
  sgemm_kernel<<<dim3((NKV * HDIM) / 128, M / 128), 256>>>(Cp, Wv, Vp, M, NKV * HDIM, LAT);

  // RoPE
  const int totQ = B * L * NH * 64;
  rope_kernel<<<(totQ + 255) / 256, 256>>>(Qp, NH, totQ);
  const int totK = B * L * NKV * 64;
  rope_kernel<<<(totK + 255) / 256, 256>>>(Kp, NKV, totK);

  // attention
  const int SMEM = (64 * 128 + 32 * 128 * 2 + 64 * 33) * 4;  // 73984 B
  cudaFuncSetAttribute(attn_kernel, cudaFuncAttributeMaxDynamicSharedMemorySize, SMEM);
  attn_kernel<<<dim3(L / 64, NH, B), 256, SMEM>>>(Qp, Kp, Vp, mask, Yp);

  // output projection
  sgemm_kernel<<<dim3(HID / 128, M / 128), 256>>>(Yp, Wo, out, M, HID, HID);
}

// round 4
// speedup vs baseline: 2.5280x; 2.5280x over previous
#include <cuda_runtime.h>
#include <cuda_bf16.h>
#include <cstdint>
#include <math.h>

#define B 2
#define L 2048
#define HID 2048
#define NH 16
#define NKV 4
#define HDIM 128
#define LAT 512
#define SCALE 0.08838834764831845f /* 1/sqrt(128) */

// ======================= helpers =======================
__device__ __forceinline__ uint32_t smem_to_u32(const void* p) {
  uint32_t a;
  asm("{ .reg .u64 t; cvta.to.shared.u64 t, %1; cvt.u32.u64 %0, t; }"
      : "=r"(a) : "l"(p));
  return a;
}
__device__ __forceinline__ void cp16(uint32_t dst, const void* src) {
  asm volatile("cp.async.cg.shared.global [%0], [%1], 16;" ::"r"(dst), "l"(src));
}
#define CP_COMMIT() asm volatile("cp.async.commit_group;" ::: "memory")
#define CP_WAIT1() asm volatile("cp.async.wait_group 1;" ::: "memory")
#define CP_WAIT0() asm volatile("cp.async.wait_group 0;" ::: "memory")

__device__ __forceinline__ void ldsm4(uint32_t addr, uint32_t* r) {
  asm volatile("ldmatrix.sync.aligned.m8n8.x4.shared.b16 {%0,%1,%2,%3}, [%4];"
               : "=r"(r[0]), "=r"(r[1]), "=r"(r[2]), "=r"(r[3]) : "r"(addr));
}
__device__ __forceinline__ void ldsm4t(uint32_t addr, uint32_t* r) {
  asm volatile(
      "ldmatrix.sync.aligned.m8n8.x4.trans.shared.b16 {%0,%1,%2,%3}, [%4];"
      : "=r"(r[0]), "=r"(r[1]), "=r"(r[2]), "=r"(r[3]) : "r"(addr));
}
__device__ __forceinline__ void mma16816(float* c, const uint32_t* a,
                                         const uint32_t* b) {
  asm volatile(
      "mma.sync.aligned.m16n8k16.row.col.f32.bf16.bf16.f32 "
      "{%0,%1,%2,%3}, {%4,%5,%6,%7}, {%8,%9}, {%0,%1,%2,%3};"
      : "+f"(c[0]), "+f"(c[1]), "+f"(c[2]), "+f"(c[3])
      : "r"(a[0]), "r"(a[1]), "r"(a[2]), "r"(a[3]), "r"(b[0]), "r"(b[1]));
}
__device__ __forceinline__ uint32_t pk2(float lo, float hi) {
  uint32_t r;
  asm("cvt.rn.bf16x2.f32 %0, %2, %1;" : "=r"(r) : "f"(lo), "f"(hi));
  return r;
}

// ======================= scratch =======================
__device__ float g_Q[(size_t)B * L * NH * HDIM];
__device__ float g_K[(size_t)B * L * NKV * HDIM];

__device__ __nv_bfloat16 g_xh[(size_t)B * L * HID], g_xl[(size_t)B * L * HID];
__device__ __nv_bfloat16 g_ch[(size_t)B * L * LAT], g_cl[(size_t)B * L * LAT];
__device__ __nv_bfloat16 g_yh[(size_t)B * L * HID], g_yl[(size_t)B * L * HID];
__device__ __nv_bfloat16 g_Qh[(size_t)B * L * NH * HDIM], g_Ql[(size_t)B * L * NH * HDIM];
__device__ __nv_bfloat16 g_Kh[(size_t)B * L * NKV * HDIM], g_Kl[(size_t)B * L * NKV * HDIM];
__device__ __nv_bfloat16 g_Vh[(size_t)B * L * NKV * HDIM], g_Vl[(size_t)B * L * NKV * HDIM];
__device__ __nv_bfloat16 g_Wqt_h[(size_t)NH * HDIM * HID], g_Wqt_l[(size_t)NH * HDIM * HID];
__device__ __nv_bfloat16 g_Wct_h[(size_t)LAT * HID], g_Wct_l[(size_t)LAT * HID];
__device__ __nv_bfloat16 g_Wkt_h[(size_t)NKV * HDIM * LAT], g_Wkt_l[(size_t)NKV * HDIM * LAT];
__device__ __nv_bfloat16 g_Wvt_h[(size_t)NKV * HDIM * LAT], g_Wvt_l[(size_t)NKV * HDIM * LAT];
__device__ __nv_bfloat16 g_Wot_h[(size_t)HID * NH * HDIM], g_Wot_l[(size_t)HID * NH * HDIM];

// ======================= preprocessing =======================
__global__ void split_kernel(const float* __restrict__ s,
                             __nv_bfloat16* __restrict__ hi,
                             __nv_bfloat16* __restrict__ lo, int n4) {
  int i = blockIdx.x * blockDim.x + threadIdx.x;
  if (i >= n4) return;
  float4 v = ((const float4*)s)[i];
  __nv_bfloat16 hx = __float2bfloat16(v.x), hy = __float2bfloat16(v.y);
  __nv_bfloat16 hz = __float2bfloat16(v.z), hw = __float2bfloat16(v.w);
  __nv_bfloat16 lx = __float2bfloat16(v.x - __bfloat162float(hx));
  __nv_bfloat16 ly = __float2bfloat16(v.y - __bfloat162float(hy));
  __nv_bfloat16 lz = __float2bfloat16(v.z - __bfloat162float(hz));
  __nv_bfloat16 lw = __float2bfloat16(v.w - __bfloat162float(hw));
  ((__nv_bfloat162*)hi)[2 * i] = __halves2bfloat162(hx, hy);
  ((__nv_bfloat162*)hi)[2 * i + 1] = __halves2bfloat162(hz, hw);
  ((__nv_bfloat162*)lo)[2 * i] = __halves2bfloat162(lx, ly);
  ((__nv_bfloat162*)lo)[2 * i + 1] = __halves2bfloat162(lz, lw);
}

// W[K,N] fp32 -> Wt[N,K] bf16 hi/lo
__global__ __launch_bounds__(256) void tsplit_kernel(
    const float* __restrict__ W, __nv_bfloat16* __restrict__ hi,
    __nv_bfloat16* __restrict__ lo, int K, int N) {
  __shared__ float t[32][33];
  const int n0 = blockIdx.x * 32, k0 = blockIdx.y * 32;
  const int tx = threadIdx.x & 31, ty = threadIdx.x >> 5;
#pragma unroll
  for (int i = 0; i < 32; i += 8)
    t[ty + i][tx] = W[(size_t)(k0 + ty + i) * N + n0 + tx];
  __syncthreads();
#pragma unroll
  for (int i = 0; i < 32; i += 8) {
    float v = t[tx][ty + i];
    __nv_bfloat16 h = __float2bfloat16(v);
    __nv_bfloat16 l = __float2bfloat16(v - __bfloat162float(h));
    const size_t o = (size_t)(n0 + ty + i) * K + k0 + tx;
    hi[o] = h;
    lo[o] = l;
  }
}

// RoPE + hi/lo split, t layout [B, L, H, 128]
__global__ void rope_split_kernel(const float* __restrict__ t,
                                  __nv_bfloat16* __restrict__ hi,
                                  __nv_bfloat16* __restrict__ lo, int H,
                                  int total) {
  int i = blockIdx.x * blockDim.x + threadIdx.x;
  if (i >= total) return;
  const int hf = i & 63;
  const int h = (i >> 6) % H;
  const int bl = i / (64 * H);
  const int l = bl & (L - 1);
  const double inv = exp(-(double)hf * 0.14391156831212788);
  const double fr = (double)l * inv;
  const float c = (float)cos(fr);
  const float s = (float)sin(fr);
  const size_t base = ((size_t)bl * H + h) * HDIM;
  const float a = t[base + hf];
  const float b2 = t[base + hf + 64];
  const float v0 = a * c - b2 * s;
  const float v1 = b2 * c + a * s;
  __nv_bfloat16 h0 = __float2bfloat16(v0), h1 = __float2bfloat16(v1);
  hi[base + hf] = h0;
  hi[base + hf + 64] = h1;
  lo[base + hf] = __float2bfloat16(v0 - __bfloat162float(h0));
  lo[base + hf + 64] = __float2bfloat16(v1 - __bfloat162float(h1));
}

// ======================= HMMA GEMM (3-term bf16 split) =======================
// C[M,N] = (Ah+Al)[M,K] @ (Bh+Bl)[N,K]^T
#define BM 128
#define BN 128
#define BK 32
#define TROW 80u
#define TILEB 10240u
#define STAGEB 40960u
#define GSMEM (2 * 40960)

__global__ __launch_bounds__(256) void mma_gemm(
    const __nv_bfloat16* __restrict__ Ah, const __nv_bfloat16* __restrict__ Al,
    const __nv_bfloat16* __restrict__ Bh, const __nv_bfloat16* __restrict__ Bl,
    float* __restrict__ Cf, __nv_bfloat16* __restrict__ Ch,
    __nv_bfloat16* __restrict__ Cl, int M, int N, int K, int mode) {
  extern __shared__ char smem[];
  const uint32_t sb = smem_to_u32(smem);
  const int tid = threadIdx.x, wid = tid >> 5, lane = tid & 31;
  const int wm = wid >> 2, wn = wid & 3;
  const int m0 = blockIdx.y * BM, n0 = blockIdx.x * BN;
  const __nv_bfloat16* pAh = Ah + (size_t)m0 * K;
  const __nv_bfloat16* pAl = Al + (size_t)m0 * K;
  const __nv_bfloat16* pBh = Bh + (size_t)n0 * K;
  const __nv_bfloat16* pBl = Bl + (size_t)n0 * K;

  float acc[4][4][4];
#pragma unroll
  for (int f = 0; f < 4; f++)
#pragma unroll
    for (int n = 0; n < 4; n++)
#pragma unroll
      for (int e = 0; e < 4; e++) acc[f][n][e] = 0.f;

  auto load_stage = [&](int k0, int buf) {
    const uint32_t base = sb + buf * STAGEB;
#pragma unroll
    for (int i = 0; i < 2; i++) {
      const int idx = i * 256 + tid;
      const int r = idx >> 2, c = idx & 3;
      const uint32_t d = base + r * TROW + c * 16u;
      const size_t go = (size_t)r * K + k0 + c * 8;
      cp16(d, pAh + go);
      cp16(d + TILEB, pAl + go);
      cp16(d + 2 * TILEB, pBh + go);
      cp16(d + 3 * TILEB, pBl + go);
    }
    CP_COMMIT();
  };

  const int S = K / BK;
  load_stage(0, 0);
  load_stage(BK, 1);

  const int rowa = wm * 64 + (lane & 15);
  const int rowb = wn * 32 + (lane & 7) + ((lane >> 4) << 3);

  for (int s = 0; s < S; s++) {
    const int buf = s & 1;
    if (s == S - 1) CP_WAIT0(); else CP_WAIT1();
    __syncthreads();
    const uint32_t abase = sb + buf * STAGEB;
    const uint32_t bbase = abase + 2 * TILEB;
#pragma unroll
    for (int ks = 0; ks < 2; ks++) {
      uint32_t ah[4][4], al[4][4], bh[2][4], bl[2][4];
      const int ca = 2 * ks + (lane >> 4);
      const int cb = 2 * ks + ((lane >> 3) & 1);
#pragma unroll
      for (int f = 0; f < 4; f++) {
        const uint32_t ad = abase + (rowa + f * 16) * TROW + ca * 16u;
        ldsm4(ad, ah[f]);
        ldsm4(ad + TILEB, al[f]);
      }
#pragma unroll
      for (int p = 0; p < 2; p++) {
        const uint32_t bd = bbase + (rowb + p * 16) * TROW + cb * 16u;
        ldsm4(bd, bh[p]);
        ldsm4(bd + TILEB, bl[p]);
      }
#pragma unroll
      for (int f = 0; f < 4; f++)
#pragma unroll
        for (int n = 0; n < 4; n++) {
          const uint32_t* bhp = &bh[n >> 1][(n & 1) * 2];
          const uint32_t* blp = &bl[n >> 1][(n & 1) * 2];
          mma16816(acc[f][n], ah[f], bhp);
          mma16816(acc[f][n], al[f], bhp);
          mma16816(acc[f][n], ah[f], blp);
        }
    }
    __syncthreads();
    if (s + 2 < S) load_stage((s + 2) * BK, buf);
  }

  // epilogue
#pragma unroll
  for (int f = 0; f < 4; f++) {
    const int row = m0 + wm * 64 + f * 16 + (lane >> 2);
#pragma unroll
    for (int n = 0; n < 4; n++) {
      const int col = n0 + wn * 32 + n * 8 + (lane & 3) * 2;
      if (mode == 0) {
        *(float2*)&Cf[(size_t)row * N + col] =
            make_float2(acc[f][n][0], acc[f][n][1]);
        *(float2*)&Cf[(size_t)(row + 8) * N + col] =
            make_float2(acc[f][n][2], acc[f][n][3]);
      } else {
#pragma unroll
        for (int half = 0; half < 2; half++) {
          const float v0 = acc[f][n][half * 2], v1 = acc[f][n][half * 2 + 1];
          __nv_bfloat16 h0 = __float2bfloat16(v0), h1 = __float2bfloat16(v1);
          __nv_bfloat16 l0 = __float2bfloat16(v0 - __bfloat162float(h0));
          __nv_bfloat16 l1 = __float2bfloat16(v1 - __bfloat162float(h1));
          const size_t o = (size_t)(row + half * 8) * N + col;
          *(__nv_bfloat162*)&Ch[o] = __halves2bfloat162(h0, h1);
          *(__nv_bfloat162*)&Cl[o] = __halves2bfloat162(l0, l1);
        }
      }
    }
  }
}

// ======================= HMMA flash attention =======================
// 128 q-rows per block, 32-key tiles, 8 warps (warp = 16 q rows).
#define AQ 128
#define AKT 32
#define ASMEM 65536

__global__ __launch_bounds__(256) void attn_mma(
    const __nv_bfloat16* __restrict__ Qh, const __nv_bfloat16* __restrict__ Ql,
    const __nv_bfloat16* __restrict__ Kh, const __nv_bfloat16* __restrict__ Kl,
    const __nv_bfloat16* __restrict__ Vh, const __nv_bfloat16* __restrict__ Vl,
    const int* __restrict__ mask, __nv_bfloat16* __restrict__ Yh,
    __nv_bfloat16* __restrict__ Yl) {
  extern __shared__ char smem[];
  const uint32_t sb = smem_to_u32(smem);
  const int qt = blockIdx.x, h = blockIdx.y, b = blockIdx.z;
  const int hkv = h >> 2;
  const int tid = threadIdx.x, w = tid >> 5, lane = tid & 31;
  const int q0 = qt * AQ;

  // ---- stage Q through smem, extract register fragments ----
  {
    const __nv_bfloat16* qhg = Qh + ((size_t)(b * L + q0) * NH + h) * 128;
    const __nv_bfloat16* qlg = Ql + ((size_t)(b * L + q0) * NH + h) * 128;
#pragma unroll
    for (int i = 0; i < 8; i++) {
      const int idx = i * 256 + tid;
      const int r = idx >> 4, c = idx & 15;
      const uint32_t d = sb + r * 256u + ((uint32_t)(c ^ (r & 7)) << 4);
      const size_t go = (size_t)r * (NH * 128) + c * 8;
      cp16(d, qhg + go);
      cp16(d + 32768u, qlg + go);
    }
    CP_COMMIT();
    CP_WAIT0();
    __syncthreads();
  }
  uint32_t qh[8][4], ql[8][4];
  {
    const int rowa = w * 16 + (lane & 15);
#pragma unroll
    for (int kd = 0; kd < 8; kd++) {
      const int ca = 2 * kd + (lane >> 4);
      const uint32_t ad = sb + rowa * 256u + ((uint32_t)(ca ^ (rowa & 7)) << 4);
      ldsm4(ad, qh[kd]);
      ldsm4(ad + 32768u, ql[kd]);
    }
  }
  __syncthreads();  // Q smem free for KV buffers

  float o[16][4];
#pragma unroll
  for (int nf = 0; nf < 16; nf++)
#pragma unroll
    for (int e = 0; e < 4; e++) o[nf][e] = 0.f;
  float m2[2] = {-1e30f, -1e30f}, ls[2] = {0.f, 0.f};

  const __nv_bfloat16* khg = Kh + ((size_t)(b * L) * NKV + hkv) * 128;
  const __nv_bfloat16* klg = Kl + ((size_t)(b * L) * NKV + hkv) * 128;
  const __nv_bfloat16* vhg = Vh + ((size_t)(b * L) * NKV + hkv) * 128;
  const __nv_bfloat16* vlg = Vl + ((size_t)(b * L) * NKV + hkv) * 128;
  const int* mrow = mask + b * L;

  auto load_kv = [&](int t, int buf) {
    const int k0 = t * AKT;
    const uint32_t base = sb + buf * 32768u;
#pragma unroll
    for (int i = 0; i < 2; i++) {
      const int idx = i * 256 + tid;
      const int r = idx >> 4, c = idx & 15;
      const uint32_t d = base + r * 256u + ((uint32_t)(c ^ (r & 7)) << 4);
      const size_t go = (size_t)(k0 + r) * (NKV * 128) + c * 8;
      cp16(d, khg + go);
      cp16(d + 8192u, klg + go);
      cp16(d + 16384u, vhg + go);
      cp16(d + 24576u, vlg + go);
    }
    CP_COMMIT();
  };

  const int nkt = qt * 4 + 4;
  load_kv(0, 0);
  load_kv(1, 1);

  const int qa = q0 + w * 16 + (lane >> 2);
  const int qb = qa + 8;
  const int rbB = (lane & 7) + ((lane >> 4) << 3);
  const int rvB = (lane & 7) + (((lane >> 3) & 1) << 3);

  for (int kt = 0; kt < nkt; kt++) {
    const int buf = kt & 1;
    const int k0 = kt * AKT;
    if (kt == nkt - 1) CP_WAIT0(); else CP_WAIT1();
    __syncthreads();

    if (k0 <= q0 + w * 16 + 15) {  // warp has at least one unmasked row
      const uint32_t kb = sb + buf * 32768u;
      float s[4][4];
#pragma unroll
      for (int n = 0; n < 4; n++)
#pragma unroll
        for (int e = 0; e < 4; e++) s[n][e] = 0.f;

      // S = Q K^T (3-pass split)
#pragma unroll
      for (int kd = 0; kd < 8; kd++) {
        const int cb = 2 * kd + ((lane >> 3) & 1);
        const uint32_t b0a = kb + (uint32_t)rbB * 256u +
                             ((uint32_t)(cb ^ (rbB & 7)) << 4);
        const uint32_t b1a = b0a + 16u * 256u;  // rows +16, same xor
        uint32_t bh0[4], bh1[4], bl0[4], bl1[4];
        ldsm4(b0a, bh0);
        ldsm4(b1a, bh1);
        ldsm4(b0a + 8192u, bl0);
        ldsm4(b1a + 8192u, bl1);
#pragma unroll
        for (int n = 0; n < 4; n++) {
          const uint32_t* bhp = (n < 2) ? &bh0[(n & 1) * 2] : &bh1[(n & 1) * 2];
          const uint32_t* blp = (n < 2) ? &bl0[(n & 1) * 2] : &bl1[(n & 1) * 2];
          mma16816(s[n], qh[kd], bhp);
          mma16816(s[n], ql[kd], bhp);
          mma16816(s[n], qh[kd], blp);
        }
      }

      // masked scale + row maxes
      float rmax[2] = {-1e30f, -1e30f};
#pragma unroll
      for (int n = 0; n < 4; n++) {
        const int col = k0 + n * 8 + (lane & 3) * 2;
        const bool mk0 = mrow[col] > 0, mk1 = mrow[col + 1] > 0;
        s[n][0] = (mk0 && col <= qa) ? s[n][0] * SCALE : -1e30f;
        s[n][1] = (mk1 && col + 1 <= qa) ? s[n][1] * SCALE : -1e30f;
        s[n][2] = (mk0 && col <= qb) ? s[n][2] * SCALE : -1e30f;
        s[n][3] = (mk1 && col + 1 <= qb) ? s[n][3] * SCALE : -1e30f;
        rmax[0] = fmaxf(rmax[0], fmaxf(s[n][0], s[n][1]));
        rmax[1] = fmaxf(rmax[1], fmaxf(s[n][2], s[n][3]));
      }
#pragma unroll
      for (int off = 1; off <= 2; off <<= 1) {
        rmax[0] = fmaxf(rmax[0], __shfl_xor_sync(0xffffffffu, rmax[0], off));
        rmax[1] = fmaxf(rmax[1], __shfl_xor_sync(0xffffffffu, rmax[1], off));
      }
      const float mn0 = fmaxf(m2[0], rmax[0]);
      const float mn1 = fmaxf(m2[1], rmax[1]);
      const float al0 = __expf(m2[0] - mn0);
      const float al1 = __expf(m2[1] - mn1);
      m2[0] = mn0;
      m2[1] = mn1;
      float ps0 = 0.f, ps1 = 0.f;
#pragma unroll
      for (int n = 0; n < 4; n++) {
        s[n][0] = __expf(s[n][0] - mn0);
        s[n][1] = __expf(s[n][1] - mn0);
        s[n][2] = __expf(s[n][2] - mn1);
        s[n][3] = __expf(s[n][3] - mn1);
        ps0 += s[n][0] + s[n][1];
        ps1 += s[n][2] + s[n][3];
      }
#pragma unroll
      for (int off = 1; off <= 2; off <<= 1) {
        ps0 += __shfl_xor_sync(0xffffffffu, ps0, off);
        ps1 += __shfl_xor_sync(0xffffffffu, ps1, off);
      }
      ls[0] = ls[0] * al0 + ps0;
      ls[1] = ls[1] * al1 + ps1;
#pragma unroll
      for (int nf = 0; nf < 16; nf++) {
        o[nf][0] *= al0;
        o[nf][1] *= al0;
        o[nf][2] *= al1;
        o[nf][3] *= al1;
      }

      // pack P -> A fragments (bf16 hi + lo)
      uint32_t pa[2][4], pal[2][4];
#pragma unroll
      for (int ks = 0; ks < 2; ks++) {
        float ph[8], pl[8];
#pragma unroll
        for (int e = 0; e < 4; e++) {
          const float v0 = s[2 * ks][e], v1 = s[2 * ks + 1][e];
          const float h0 = __bfloat162float(__float2bfloat16(v0));
          const float h1 = __bfloat162float(__float2bfloat16(v1));
          ph[e] = h0;
          ph[4 + e] = h1;
          pl[e] = v0 - h0;
          pl[4 + e] = v1 - h1;
        }
        pa[ks][0] = pk2(ph[0], ph[1]);
        pa[ks][1] = pk2(ph[2], ph[3]);
        pa[ks][2] = pk2(ph[4], ph[5]);
        pa[ks][3] = pk2(ph[6], ph[7]);
        pal[ks][0] = pk2(pl[0], pl[1]);
        pal[ks][1] = pk2(pl[2], pl[3]);
        pal[ks][2] = pk2(pl[4], pl[5]);
        pal[ks][3] = pk2(pl[6], pl[7]);
      }

      // O += P V (3-pass: Ph*Vh + Pl*Vh + Ph*Vl)
      const uint32_t vb = kb + 16384u;
#pragma unroll
      for (int ks = 0; ks < 2; ks++) {
        const int rowv = 16 * ks + rvB;
#pragma unroll
        for (int j = 0; j < 8; j++) {
          const int cv = 2 * j + (lane >> 4);
          const uint32_t a = vb + (uint32_t)rowv * 256u +
                             ((uint32_t)(cv ^ (rowv & 7)) << 4);
          uint32_t vhf[4], vlf[4];
          ldsm4t(a, vhf);
          ldsm4t(a + 8192u, vlf);
          mma16816(o[2 * j], pa[ks], &vhf[0]);
          mma16816(o[2 * j + 1], pa[ks], &vhf[2]);
          mma16816(o[2 * j], pal[ks], &vhf[0]);
          mma16816(o[2 * j + 1], pal[ks], &vhf[2]);
          mma16816(o[2 * j], pa[ks], &vlf[0]);
          mma16816(o[2 * j + 1], pa[ks], &vlf[2]);
        }
      }
    }

    __syncthreads();
    if (kt + 2 < nkt) load_kv(kt + 2, buf);
  }

  // ---- normalize + write hi/lo Y ----
  const float inv0 = 1.f / ls[0], inv1 = 1.f / ls[1];
  const size_t rA = (size_t)(b * L + qa) * (size_t)HID + h * 128;
  const size_t rB = rA + (size_t)8 * HID;
#pragma unroll
  for (int nf = 0; nf < 16; nf++) {
    const int d = nf * 8 + (lane & 3) * 2;
    float y0 = o[nf][0] * inv0, y1 = o[nf][1] * inv0;
    float y2 = o[nf][2] * inv1, y3 = o[nf][3] * inv1;
    __nv_bfloat16 h0 = __float2bfloat16(y0), h1 = __float2bfloat16(y1);
    __nv_bfloat16 h2 = __float2bfloat16(y2), h3 = __float2bfloat16(y3);
    *(__nv_bfloat162*)&Yh[rA + d] = __halves2bfloat162(h0, h1);
    *(__nv_bfloat162*)&Yh[rB + d] = __halves2bfloat162(h2, h3);
    *(__nv_bfloat162*)&Yl[rA + d] = __halves2bfloat162(
        __float2bfloat16(y0 - __bfloat162float(h0)),
        __float2bfloat16(y1 - __bfloat162float(h1)));
    *(__nv_bfloat162*)&Yl[rB + d] = __halves2bfloat162(
        __float2bfloat16(y2 - __bfloat162float(h2)),
        __float2bfloat16(y3 - __bfloat162float(h3)));
  }
}

// ======================= launch =======================
extern "C" void kernel_launch(void* const* d_in, const int* in_sizes, int n_in,
                              void* d_out, int out_size) {
  const float* x = (const float*)d_in[0];
  const float* Wq = (const float*)d_in[1];
  const float* Wc = (const float*)d_in[2];
  const float* Wk = (const float*)d_in[3];
  const float* Wv = (const float*)d_in[4];
  const float* Wo = (const float*)d_in[5];
  const int* mask = (const int*)d_in[6];
  float* out = (float*)d_out;

  float *Qp, *Kp;
  cudaGetSymbolAddress((void**)&Qp, g_Q);
  cudaGetSymbolAddress((void**)&Kp, g_K);
  __nv_bfloat16 *xh, *xl, *ch, *cl, *yh, *yl, *qhh, *qll, *khh, *kll, *vhh, *vll;
  __nv_bfloat16 *wqh, *wql, *wch, *wcl, *wkh, *wkl, *wvh, *wvl, *woh, *wol;
  cudaGetSymbolAddress((void**)&xh, g_xh);
  cudaGetSymbolAddress((void**)&xl, g_xl);
  cudaGetSymbolAddress((void**)&ch, g_ch);
  cudaGetSymbolAddress((void**)&cl, g_cl);
  cudaGetSymbolAddress((void**)&yh, g_yh);
  cudaGetSymbolAddress((void**)&yl, g_yl);
  cudaGetSymbolAddress((void**)&qhh, g_Qh);
  cudaGetSymbolAddress((void**)&qll, g_Ql);
  cudaGetSymbolAddress((void**)&khh, g_Kh);
  cudaGetSymbolAddress((void**)&kll, g_Kl);
  cudaGetSymbolAddress((void**)&vhh, g_Vh);
  cudaGetSymbolAddress((void**)&vll, g_Vl);
  cudaGetSymbolAddress((void**)&wqh, g_Wqt_h);
  cudaGetSymbolAddress((void**)&wql, g_Wqt_l);
  cudaGetSymbolAddress((void**)&wch, g_Wct_h);
  cudaGetSymbolAddress((void**)&wcl, g_Wct_l);
  cudaGetSymbolAddress((void**)&wkh, g_Wkt_h);
  cudaGetSymbolAddress((void**)&wkl, g_Wkt_l);
  cudaGetSymbolAddress((void**)&wvh, g_Wvt_h);
  cudaGetSymbolAddress((void**)&wvl, g_Wvt_l);
  cudaGetSymbolAddress((void**)&woh, g_Wot_h);
  cudaGetSymbolAddress((void**)&wol, g_Wot_l);

  const int M = B * L;  // 4096

  cudaFuncSetAttribute(mma_gemm, cudaFuncAttributeMaxDynamicSharedMemorySize, GSMEM);
  cudaFuncSetAttribute(attn_mma, cudaFuncAttributeMaxDynamicSharedMemorySize, ASMEM);

  // splits
  split_kernel<<<(M * HID / 4 + 255) / 256, 256>>>(x, xh, xl, M * HID / 4);
  tsplit_kernel<<<dim3((NH * HDIM) / 32, HID / 32), 256>>>(Wq, wqh, wql, HID, NH * HDIM);
  tsplit_kernel<<<dim3(LAT / 32, HID / 32), 256>>>(Wc, wch, wcl, HID, LAT);
  tsplit_kernel<<<dim3((NKV * HDIM) / 32, LAT / 32), 256>>>(Wk, wkh, wkl, LAT, NKV * HDIM);
  tsplit_kernel<<<dim3((NKV * HDIM) / 32, LAT / 32), 256>>>(Wv, wvh, wvl, LAT, NKV * HDIM);
  tsplit_kernel<<<dim3(HID / 32, (NH * HDIM) / 32), 256>>>(Wo, woh, wol, NH * HDIM, HID);

  // projections
  mma_gemm<<<dim3((NH * HDIM) / BN, M / BM), 256, GSMEM>>>(
      xh, xl, wqh, wql, Qp, nullptr, nullptr, M, NH * HDIM, HID, 0);
  mma_gemm<<<dim3(LAT / BN, M / BM), 256, GSMEM>>>(
      xh, xl, wch, wcl, nullptr, ch, cl, M, LAT, HID, 1);
  mma_gemm<<<dim3((NKV * HDIM) / BN, M / BM), 256, GSMEM>>>(
      ch, cl, wkh, wkl, Kp, nullptr, nullptr, M, NKV * HDIM, LAT, 0);
  mma_gemm<<<dim3((NKV * HDIM) / BN, M / BM), 256, GSMEM>>>(
      ch, cl, wvh, wvl, nullptr, vhh, vll, M, NKV * HDIM, LAT, 1);

  // RoPE + split
  const int totQ = B * L * NH * 64;
  rope_split_kernel<<<(totQ + 255) / 256, 256>>>(Qp, qhh, qll, NH, totQ);
  const int totK = B * L * NKV * 64;
  rope_split_kernel<<<(totK + 255) / 256, 256>>>(Kp, khh, kll, NKV, totK);

  // attention
  attn_mma<<<dim3(L / AQ, NH, B), 256, ASMEM>>>(qhh, qll, khh, kll, vhh, vll,
                                                mask, yh, yl);

  // output projection
  mma_gemm<<<dim3(HID / BN, M / BM), 256, GSMEM>>>(
      yh, yl, woh, wol, out, nullptr, nullptr, M, HID, HID, 0);
}

// round 5
// speedup vs baseline: 4.1137x; 1.6273x over previous
#include <cuda_runtime.h>
#include <cuda_bf16.h>
#include <cuda_fp16.h>
#include <cstdint>
#include <math.h>

#define B 2
#define L 2048
#define HID 2048
#define NH 16
#define NKV 4
#define HDIM 128
#define LAT 512
#define SCALE 0.08838834764831845f /* 1/sqrt(128) */

// ======================= helpers =======================
__device__ __forceinline__ uint32_t smem_to_u32(const void* p) {
  uint32_t a;
  asm("{ .reg .u64 t; cvta.to.shared.u64 t, %1; cvt.u32.u64 %0, t; }"
      : "=r"(a) : "l"(p));
  return a;
}
__device__ __forceinline__ void cp16(uint32_t dst, const void* src) {
  asm volatile("cp.async.cg.shared.global [%0], [%1], 16;" ::"r"(dst), "l"(src));
}
#define CP_COMMIT() asm volatile("cp.async.commit_group;" ::: "memory")
#define CP_WAIT1() asm volatile("cp.async.wait_group 1;" ::: "memory")
#define CP_WAIT0() asm volatile("cp.async.wait_group 0;" ::: "memory")

__device__ __forceinline__ void ldsm4(uint32_t addr, uint32_t* r) {
  asm volatile("ldmatrix.sync.aligned.m8n8.x4.shared.b16 {%0,%1,%2,%3}, [%4];"
               : "=r"(r[0]), "=r"(r[1]), "=r"(r[2]), "=r"(r[3]) : "r"(addr));
}
__device__ __forceinline__ void ldsm4t(uint32_t addr, uint32_t* r) {
  asm volatile(
      "ldmatrix.sync.aligned.m8n8.x4.trans.shared.b16 {%0,%1,%2,%3}, [%4];"
      : "=r"(r[0]), "=r"(r[1]), "=r"(r[2]), "=r"(r[3]) : "r"(addr));
}
// bf16 mma
__device__ __forceinline__ void mma16816(float* c, const uint32_t* a,
                                         const uint32_t* b) {
  asm volatile(
      "mma.sync.aligned.m16n8k16.row.col.f32.bf16.bf16.f32 "
      "{%0,%1,%2,%3}, {%4,%5,%6,%7}, {%8,%9}, {%0,%1,%2,%3};"
      : "+f"(c[0]), "+f"(c[1]), "+f"(c[2]), "+f"(c[3])
      : "r"(a[0]), "r"(a[1]), "r"(a[2]), "r"(a[3]), "r"(b[0]), "r"(b[1]));
}
// fp16 mma
__device__ __forceinline__ void mma16816h(float* c, const uint32_t* a,
                                          const uint32_t* b) {
  asm volatile(
      "mma.sync.aligned.m16n8k16.row.col.f32.f16.f16.f32 "
      "{%0,%1,%2,%3}, {%4,%5,%6,%7}, {%8,%9}, {%0,%1,%2,%3};"
      : "+f"(c[0]), "+f"(c[1]), "+f"(c[2]), "+f"(c[3])
      : "r"(a[0]), "r"(a[1]), "r"(a[2]), "r"(a[3]), "r"(b[0]), "r"(b[1]));
}
__device__ __forceinline__ uint32_t pk2h(float lo, float hi) {
  __half2 h = __floats2half2_rn(lo, hi);
  return *(uint32_t*)&h;
}

// ======================= scratch =======================
__device__ float g_Q[(size_t)B * L * NH * HDIM];
__device__ float g_K[(size_t)B * L * NKV * HDIM];

__device__ __half g_xf[(size_t)B * L * HID];
__device__ __half g_Qf[(size_t)B * L * NH * HDIM];
__device__ __half g_Kf[(size_t)B * L * NKV * HDIM];
__device__ __half g_Vf[(size_t)B * L * NKV * HDIM];
__device__ __half g_Yf[(size_t)B * L * HID];
__device__ __half g_Wqt_f[(size_t)NH * HDIM * HID];
__device__ __half g_Wot_f[(size_t)HID * NH * HDIM];

__device__ __nv_bfloat16 g_xh[(size_t)B * L * HID], g_xl[(size_t)B * L * HID];
__device__ __nv_bfloat16 g_ch[(size_t)B * L * LAT], g_cl[(size_t)B * L * LAT];
__device__ __nv_bfloat16 g_Wct_h[(size_t)LAT * HID], g_Wct_l[(size_t)LAT * HID];
__device__ __nv_bfloat16 g_Wkt_h[(size_t)NKV * HDIM * LAT], g_Wkt_l[(size_t)NKV * HDIM * LAT];
__device__ __nv_bfloat16 g_Wvt_h[(size_t)NKV * HDIM * LAT], g_Wvt_l[(size_t)NKV * HDIM * LAT];

// ======================= preprocessing =======================
// x -> fp16 single + bf16 hi/lo
__global__ void split3_kernel(const float* __restrict__ s,
                              __half* __restrict__ f,
                              __nv_bfloat16* __restrict__ hi,
                              __nv_bfloat16* __restrict__ lo, int n4) {
  int i = blockIdx.x * blockDim.x + threadIdx.x;
  if (i >= n4) return;
  float4 v = ((const float4*)s)[i];
  ((__half2*)f)[2 * i] = __floats2half2_rn(v.x, v.y);
  ((__half2*)f)[2 * i + 1] = __floats2half2_rn(v.z, v.w);
  __nv_bfloat16 hx = __float2bfloat16(v.x), hy = __float2bfloat16(v.y);
  __nv_bfloat16 hz = __float2bfloat16(v.z), hw = __float2bfloat16(v.w);
  ((__nv_bfloat162*)hi)[2 * i] = __halves2bfloat162(hx, hy);
  ((__nv_bfloat162*)hi)[2 * i + 1] = __halves2bfloat162(hz, hw);
  ((__nv_bfloat162*)lo)[2 * i] =
      __halves2bfloat162(__float2bfloat16(v.x - __bfloat162float(hx)),
                         __float2bfloat16(v.y - __bfloat162float(hy)));
  ((__nv_bfloat162*)lo)[2 * i + 1] =
      __halves2bfloat162(__float2bfloat16(v.z - __bfloat162float(hz)),
                         __float2bfloat16(v.w - __bfloat162float(hw)));
}

// W[K,N] fp32 -> Wt[N,K] bf16 hi/lo
__global__ __launch_bounds__(256) void tsplit_kernel(
    const float* __restrict__ W, __nv_bfloat16* __restrict__ hi,
    __nv_bfloat16* __restrict__ lo, int K, int N) {
  __shared__ float t[32][33];
  const int n0 = blockIdx.x * 32, k0 = blockIdx.y * 32;
  const int tx = threadIdx.x & 31, ty = threadIdx.x >> 5;
#pragma unroll
  for (int i = 0; i < 32; i += 8)
    t[ty + i][tx] = W[(size_t)(k0 + ty + i) * N + n0 + tx];
  __syncthreads();
#pragma unroll
  for (int i = 0; i < 32; i += 8) {
    float v = t[tx][ty + i];
    __nv_bfloat16 h = __float2bfloat16(v);
    __nv_bfloat16 l = __float2bfloat16(v - __bfloat162float(h));
    const size_t o = (size_t)(n0 + ty + i) * K + k0 + tx;
    hi[o] = h;
    lo[o] = l;
  }
}

// W[K,N] fp32 -> Wt[N,K] fp16
__global__ __launch_bounds__(256) void tsplit_f16_kernel(
    const float* __restrict__ W, __half* __restrict__ f, int K, int N) {
  __shared__ float t[32][33];
  const int n0 = blockIdx.x * 32, k0 = blockIdx.y * 32;
  const int tx = threadIdx.x & 31, ty = threadIdx.x >> 5;
#pragma unroll
  for (int i = 0; i < 32; i += 8)
    t[ty + i][tx] = W[(size_t)(k0 + ty + i) * N + n0 + tx];
  __syncthreads();
#pragma unroll
  for (int i = 0; i < 32; i += 8)
    f[(size_t)(n0 + ty + i) * K + k0 + tx] = __float2half(t[tx][ty + i]);
}

// RoPE fp32 -> fp16, layout [B, L, H, 128]
__global__ void rope_f16_kernel(const float* __restrict__ t,
                                __half* __restrict__ f, int H, int total) {
  int i = blockIdx.x * blockDim.x + threadIdx.x;
  if (i >= total) return;
  const int hf = i & 63;
  const int h = (i >> 6) % H;
  const int bl = i / (64 * H);
  const int l = bl & (L - 1);
  const double inv = exp(-(double)hf * 0.14391156831212788);
  const double fr = (double)l * inv;
  const float c = (float)cos(fr);
  const float s = (float)sin(fr);
  const size_t base = ((size_t)bl * H + h) * HDIM;
  const float a = t[base + hf];
  const float b2 = t[base + hf + 64];
  f[base + hf] = __float2half(a * c - b2 * s);
  f[base + hf + 64] = __float2half(b2 * c + a * s);
}

// ======================= 3-term bf16 split GEMM (small projections) ==========
#define BM 128
#define BN 128
#define BK 32
#define TROW 80u
#define TILEB 10240u
#define STAGEB 40960u
#define GSMEM (2 * 40960)

__global__ __launch_bounds__(256) void mma_gemm(
    const __nv_bfloat16* __restrict__ Ah, const __nv_bfloat16* __restrict__ Al,
    const __nv_bfloat16* __restrict__ Bh, const __nv_bfloat16* __restrict__ Bl,
    float* __restrict__ Cf, __nv_bfloat16* __restrict__ Ch,
    __nv_bfloat16* __restrict__ Cl, __half* __restrict__ Cf16, int M, int N,
    int K, int mode) {
  extern __shared__ char smem[];
  const uint32_t sb = smem_to_u32(smem);
  const int tid = threadIdx.x, wid = tid >> 5, lane = tid & 31;
  const int wm = wid >> 2, wn = wid & 3;
  const int m0 = blockIdx.y * BM, n0 = blockIdx.x * BN;
  const __nv_bfloat16* pAh = Ah + (size_t)m0 * K;
  const __nv_bfloat16* pAl = Al + (size_t)m0 * K;
  const __nv_bfloat16* pBh = Bh + (size_t)n0 * K;
  const __nv_bfloat16* pBl = Bl + (size_t)n0 * K;

  float acc[4][4][4];
#pragma unroll
  for (int f = 0; f < 4; f++)
#pragma unroll
    for (int n = 0; n < 4; n++)
#pragma unroll
      for (int e = 0; e < 4; e++) acc[f][n][e] = 0.f;

  auto load_stage = [&](int k0, int buf) {
    const uint32_t base = sb + buf * STAGEB;
#pragma unroll
    for (int i = 0; i < 2; i++) {
      const int idx = i * 256 + tid;
      const int r = idx >> 2, c = idx & 3;
      const uint32_t d = base + r * TROW + c * 16u;
      const size_t go = (size_t)r * K + k0 + c * 8;
      cp16(d, pAh + go);
      cp16(d + TILEB, pAl + go);
      cp16(d + 2 * TILEB, pBh + go);
      cp16(d + 3 * TILEB, pBl + go);
    }
    CP_COMMIT();
  };

  const int S = K / BK;
  load_stage(0, 0);
  load_stage(BK, 1);

  const int rowa = wm * 64 + (lane & 15);
  const int rowb = wn * 32 + (lane & 7) + ((lane >> 4) << 3);

  for (int s = 0; s < S; s++) {
    const int buf = s & 1;
    if (s == S - 1) CP_WAIT0(); else CP_WAIT1();
    __syncthreads();
    const uint32_t abase = sb + buf * STAGEB;
    const uint32_t bbase = abase + 2 * TILEB;
#pragma unroll
    for (int ks = 0; ks < 2; ks++) {
      uint32_t ah[4][4], al[4][4], bh[2][4], bl[2][4];
      const int ca = 2 * ks + (lane >> 4);
      const int cb = 2 * ks + ((lane >> 3) & 1);
#pragma unroll
      for (int f = 0; f < 4; f++) {
        const uint32_t ad = abase + (rowa + f * 16) * TROW + ca * 16u;
        ldsm4(ad, ah[f]);
        ldsm4(ad + TILEB, al[f]);
      }
#pragma unroll
      for (int p = 0; p < 2; p++) {
        const uint32_t bd = bbase + (rowb + p * 16) * TROW + cb * 16u;
        ldsm4(bd, bh[p]);
        ldsm4(bd + TILEB, bl[p]);
      }
#pragma unroll
      for (int f = 0; f < 4; f++)
#pragma unroll
        for (int n = 0; n < 4; n++) {
          const uint32_t* bhp = &bh[n >> 1][(n & 1) * 2];
          const uint32_t* blp = &bl[n >> 1][(n & 1) * 2];
          mma16816(acc[f][n], ah[f], bhp);
          mma16816(acc[f][n], al[f], bhp);
          mma16816(acc[f][n], ah[f], blp);
        }
    }
    __syncthreads();
    if (s + 2 < S) load_stage((s + 2) * BK, buf);
  }

  // epilogue
#pragma unroll
  for (int f = 0; f < 4; f++) {
    const int row = m0 + wm * 64 + f * 16 + (lane >> 2);
#pragma unroll
    for (int n = 0; n < 4; n++) {
      const int col = n0 + wn * 32 + n * 8 + (lane & 3) * 2;
      if (mode == 0) {
        *(float2*)&Cf[(size_t)row * N + col] =
            make_float2(acc[f][n][0], acc[f][n][1]);
        *(float2*)&Cf[(size_t)(row + 8) * N + col] =
            make_float2(acc[f][n][2], acc[f][n][3]);
      } else if (mode == 1) {
#pragma unroll
        for (int half = 0; half < 2; half++) {
          const float v0 = acc[f][n][half * 2], v1 = acc[f][n][half * 2 + 1];
          __nv_bfloat16 h0 = __float2bfloat16(v0), h1 = __float2bfloat16(v1);
          __nv_bfloat16 l0 = __float2bfloat16(v0 - __bfloat162float(h0));
          __nv_bfloat16 l1 = __float2bfloat16(v1 - __bfloat162float(h1));
          const size_t o = (size_t)(row + half * 8) * N + col;
          *(__nv_bfloat162*)&Ch[o] = __halves2bfloat162(h0, h1);
          *(__nv_bfloat162*)&Cl[o] = __halves2bfloat162(l0, l1);
        }
      } else {
        *(__half2*)&Cf16[(size_t)row * N + col] =
            __floats2half2_rn(acc[f][n][0], acc[f][n][1]);
        *(__half2*)&Cf16[(size_t)(row + 8) * N + col] =
            __floats2half2_rn(acc[f][n][2], acc[f][n][3]);
      }
    }
  }
}

// ======================= single-pass fp16 GEMM (big projections) ============
// C[M,N] = A[M,K] @ B[N,K]^T, fp16 in, fp32 out. BK=64, 128B rows, XOR swizzle.
#define FBK 64
#define FTILEB 16384u
#define FSTAGEB 32768u
#define GSMEM_F16 65536

__global__ __launch_bounds__(256) void mma_gemm_f16(
    const __half* __restrict__ A, const __half* __restrict__ Bm,
    float* __restrict__ C, int M, int N, int K) {
  extern __shared__ char smem[];
  const uint32_t sb = smem_to_u32(smem);
  const int tid = threadIdx.x, wid = tid >> 5, lane = tid & 31;
  const int wm = wid >> 2, wn = wid & 3;
  const int m0 = blockIdx.y * BM, n0 = blockIdx.x * BN;
  const __half* pA = A + (size_t)m0 * K;
  const __half* pB = Bm + (size_t)n0 * K;

  float acc[4][4][4];
#pragma unroll
  for (int f = 0; f < 4; f++)
#pragma unroll
    for (int n = 0; n < 4; n++)
#pragma unroll
      for (int e = 0; e < 4; e++) acc[f][n][e] = 0.f;

  auto load_stage = [&](int k0, int buf) {
    const uint32_t base = sb + buf * FSTAGEB;
#pragma unroll
    for (int i = 0; i < 4; i++) {
      const int idx = i * 256 + tid;
      const int r = idx >> 3, c = idx & 7;
      const uint32_t d = base + r * 128u + ((uint32_t)(c ^ (r & 7)) << 4);
      const size_t go = (size_t)r * K + k0 + c * 8;
      cp16(d, pA + go);
      cp16(d + FTILEB, pB + go);
    }
    CP_COMMIT();
  };

  const int S = K / FBK;
  load_stage(0, 0);
  load_stage(FBK, 1);

  const int rowa = wm * 64 + (lane & 15);
  const int rowb = wn * 32 + (lane & 7) + ((lane >> 4) << 3);

  for (int s = 0; s < S; s++) {
    const int buf = s & 1;
    if (s == S - 1) CP_WAIT0(); else CP_WAIT1();
    __syncthreads();
    const uint32_t abase = sb + buf * FSTAGEB;
    const uint32_t bbase = abase + FTILEB;
#pragma unroll
    for (int ks = 0; ks < 4; ks++) {
      uint32_t ah[4][4], bh[2][4];
      const int ca = 2 * ks + (lane >> 4);
      const int cb = 2 * ks + ((lane >> 3) & 1);
#pragma unroll
      for (int f = 0; f < 4; f++) {
        const int rr = rowa + f * 16;
        ldsm4(abase + rr * 128u + ((uint32_t)(ca ^ (rr & 7)) << 4), ah[f]);
      }
#pragma unroll
      for (int p = 0; p < 2; p++) {
        const int rr = rowb + p * 16;
        ldsm4(bbase + rr * 128u + ((uint32_t)(cb ^ (rr & 7)) << 4), bh[p]);
      }
#pragma unroll
      for (int f = 0; f < 4; f++)
#pragma unroll
        for (int n = 0; n < 4; n++)
          mma16816h(acc[f][n], ah[f], &bh[n >> 1][(n & 1) * 2]);
    }
    __syncthreads();
    if (s + 2 < S) load_stage((s + 2) * FBK, buf);
  }

#pragma unroll
  for (int f = 0; f < 4; f++) {
    const int row = m0 + wm * 64 + f * 16 + (lane >> 2);
#pragma unroll
    for (int n = 0; n < 4; n++) {
      const int col = n0 + wn * 32 + n * 8 + (lane & 3) * 2;
      *(float2*)&C[(size_t)row * N + col] =
          make_float2(acc[f][n][0], acc[f][n][1]);
      *(float2*)&C[(size_t)(row + 8) * N + col] =
          make_float2(acc[f][n][2], acc[f][n][3]);
    }
  }
}

// ======================= fp16 flash attention =======================
// 128 q-rows per block, 32-key tiles, 8 warps (warp = 16 q rows).
#define AQ 128
#define AKT 32
#define ASMEM 32768

__global__ __launch_bounds__(256) void attn_mma(
    const __half* __restrict__ Qf, const __half* __restrict__ Kf,
    const __half* __restrict__ Vf, const int* __restrict__ mask,
    __half* __restrict__ Yf) {
  extern __shared__ char smem[];
  const uint32_t sb = smem_to_u32(smem);
  const int qt = blockIdx.x, h = blockIdx.y, b = blockIdx.z;
  const int hkv = h >> 2;
  const int tid = threadIdx.x, w = tid >> 5, lane = tid & 31;
  const int q0 = qt * AQ;

  // ---- stage Q through smem, extract register fragments ----
  {
    const __half* qg = Qf + ((size_t)(b * L + q0) * NH + h) * 128;
#pragma unroll
    for (int i = 0; i < 8; i++) {
      const int idx = i * 256 + tid;
      const int r = idx >> 4, c = idx & 15;
      const uint32_t d = sb + r * 256u + ((uint32_t)(c ^ (r & 7)) << 4);
      cp16(d, qg + (size_t)r * (NH * 128) + c * 8);
    }
    CP_COMMIT();
    CP_WAIT0();
    __syncthreads();
  }
  uint32_t qh[8][4];
  {
    const int rowa = w * 16 + (lane & 15);
#pragma unroll
    for (int kd = 0; kd < 8; kd++) {
      const int ca = 2 * kd + (lane >> 4);
      ldsm4(sb + rowa * 256u + ((uint32_t)(ca ^ (rowa & 7)) << 4), qh[kd]);
    }
  }
  __syncthreads();  // Q smem free for KV buffers

  float o[16][4];
#pragma unroll
  for (int nf = 0; nf < 16; nf++)
#pragma unroll
    for (int e = 0; e < 4; e++) o[nf][e] = 0.f;
  float m2[2] = {-1e30f, -1e30f}, ls[2] = {0.f, 0.f};

  const __half* khg = Kf + ((size_t)(b * L) * NKV + hkv) * 128;
  const __half* vhg = Vf + ((size_t)(b * L) * NKV + hkv) * 128;
  const int* mrow = mask + b * L;

  auto load_kv = [&](int t, int buf) {
    const int k0 = t * AKT;
    const uint32_t base = sb + buf * 16384u;
#pragma unroll
    for (int i = 0; i < 2; i++) {
      const int idx = i * 256 + tid;
      const int r = idx >> 4, c = idx & 15;
      const uint32_t d = base + r * 256u + ((uint32_t)(c ^ (r & 7)) << 4);
      const size_t go = (size_t)(k0 + r) * (NKV * 128) + c * 8;
      cp16(d, khg + go);
      cp16(d + 8192u, vhg + go);
    }
    CP_COMMIT();
  };

  const int nkt = qt * 4 + 4;
  load_kv(0, 0);
  load_kv(1, 1);

  const int qa = q0 + w * 16 + (lane >> 2);
  const int qb = qa + 8;
  const int rbB = (lane & 7) + ((lane >> 4) << 3);
  const int rvB = (lane & 7) + (((lane >> 3) & 1) << 3);

  for (int kt = 0; kt < nkt; kt++) {
    const int buf = kt & 1;
    const int k0 = kt * AKT;
    if (kt == nkt - 1) CP_WAIT0(); else CP_WAIT1();
    __syncthreads();

    if (k0 <= q0 + w * 16 + 15) {
      const uint32_t kb = sb + buf * 16384u;
      float s[4][4];
#pragma unroll
      for (int n = 0; n < 4; n++)
#pragma unroll
        for (int e = 0; e < 4; e++) s[n][e] = 0.f;

      // S = Q K^T (single pass fp16)
#pragma unroll
      for (int kd = 0; kd < 8; kd++) {
        const int cb = 2 * kd + ((lane >> 3) & 1);
        const uint32_t b0a =
            kb + (uint32_t)rbB * 256u + ((uint32_t)(cb ^ (rbB & 7)) << 4);
        uint32_t bh0[4], bh1[4];
        ldsm4(b0a, bh0);
        ldsm4(b0a + 16u * 256u, bh1);
#pragma unroll
        for (int n = 0; n < 4; n++) {
          const uint32_t* bp = (n < 2) ? &bh0[(n & 1) * 2] : &bh1[(n & 1) * 2];
          mma16816h(s[n], qh[kd], bp);
        }
      }

      // masked scale + row maxes
      float rmax[2] = {-1e30f, -1e30f};
#pragma unroll
      for (int n = 0; n < 4; n++) {
        const int col = k0 + n * 8 + (lane & 3) * 2;
        const bool mk0 = mrow[col] > 0, mk1 = mrow[col + 1] > 0;
        s[n][0] = (mk0 && col <= qa) ? s[n][0] * SCALE : -1e30f;
        s[n][1] = (mk1 && col + 1 <= qa) ? s[n][1] * SCALE : -1e30f;
        s[n][2] = (mk0 && col <= qb) ? s[n][2] * SCALE : -1e30f;
        s[n][3] = (mk1 && col + 1 <= qb) ? s[n][3] * SCALE : -1e30f;
        rmax[0] = fmaxf(rmax[0], fmaxf(s[n][0], s[n][1]));
        rmax[1] = fmaxf(rmax[1], fmaxf(s[n][2], s[n][3]));
      }
#pragma unroll
      for (int off = 1; off <= 2; off <<= 1) {
        rmax[0] = fmaxf(rmax[0], __shfl_xor_sync(0xffffffffu, rmax[0], off));
        rmax[1] = fmaxf(rmax[1], __shfl_xor_sync(0xffffffffu, rmax[1], off));
      }
      const float mn0 = fmaxf(m2[0], rmax[0]);
      const float mn1 = fmaxf(m2[1], rmax[1]);
      const float al0 = __expf(m2[0] - mn0);
      const float al1 = __expf(m2[1] - mn1);
      m2[0] = mn0;
      m2[1] = mn1;
      float ps0 = 0.f, ps1 = 0.f;
#pragma unroll
      for (int n = 0; n < 4; n++) {
        s[n][0] = __expf(s[n][0] - mn0);
        s[n][1] = __expf(s[n][1] - mn0);
        s[n][2] = __expf(s[n][2] - mn1);
        s[n][3] = __expf(s[n][3] - mn1);
        ps0 += s[n][0] + s[n][1];
        ps1 += s[n][2] + s[n][3];
      }
#pragma unroll
      for (int off = 1; off <= 2; off <<= 1) {
        ps0 += __shfl_xor_sync(0xffffffffu, ps0, off);
        ps1 += __shfl_xor_sync(0xffffffffu, ps1, off);
      }
      ls[0] = ls[0] * al0 + ps0;
      ls[1] = ls[1] * al1 + ps1;
#pragma unroll
      for (int nf = 0; nf < 16; nf++) {
        o[nf][0] *= al0;
        o[nf][1] *= al0;
        o[nf][2] *= al1;
        o[nf][3] *= al1;
      }

      // pack P -> fp16 A fragments
      uint32_t pa[2][4];
#pragma unroll
      for (int ks = 0; ks < 2; ks++) {
        pa[ks][0] = pk2h(s[2 * ks][0], s[2 * ks][1]);
        pa[ks][1] = pk2h(s[2 * ks][2], s[2 * ks][3]);
        pa[ks][2] = pk2h(s[2 * ks + 1][0], s[2 * ks + 1][1]);
        pa[ks][3] = pk2h(s[2 * ks + 1][2], s[2 * ks + 1][3]);
      }

      // O += P V (single pass fp16)
      const uint32_t vb = kb + 8192u;
#pragma unroll
      for (int ks = 0; ks < 2; ks++) {
        const int rowv = 16 * ks + rvB;
#pragma unroll
        for (int j = 0; j < 8; j++) {
          const int cv = 2 * j + (lane >> 4);
          uint32_t vhf[4];
          ldsm4t(vb + (uint32_t)rowv * 256u +
                     ((uint32_t)(cv ^ (rowv & 7)) << 4),
                 vhf);
          mma16816h(o[2 * j], pa[ks], &vhf[0]);
          mma16816h(o[2 * j + 1], pa[ks], &vhf[2]);
        }
      }
    }

    __syncthreads();
    if (kt + 2 < nkt) load_kv(kt + 2, buf);
  }

  // ---- normalize + write fp16 Y ----
  const float inv0 = 1.f / ls[0], inv1 = 1.f / ls[1];
  const size_t rA = (size_t)(b * L + qa) * (size_t)HID + h * 128;
  const size_t rB = rA + (size_t)8 * HID;
#pragma unroll
  for (int nf = 0; nf < 16; nf++) {
    const int d = nf * 8 + (lane & 3) * 2;
    *(__half2*)&Yf[rA + d] = __floats2half2_rn(o[nf][0] * inv0, o[nf][1] * inv0);
    *(__half2*)&Yf[rB + d] = __floats2half2_rn(o[nf][2] * inv1, o[nf][3] * inv1);
  }
}

// ======================= launch =======================
extern "C" void kernel_launch(void* const* d_in, const int* in_sizes, int n_in,
                              void* d_out, int out_size) {
  const float* x = (const float*)d_in[0];
  const float* Wq = (const float*)d_in[1];
  const float* Wc = (const float*)d_in[2];
  const float* Wk = (const float*)d_in[3];
  const float* Wv = (const float*)d_in[4];
  const float* Wo = (const float*)d_in[5];
  const int* mask = (const int*)d_in[6];
  float* out = (float*)d_out;

  float *Qp, *Kp;
  cudaGetSymbolAddress((void**)&Qp, g_Q);
  cudaGetSymbolAddress((void**)&Kp, g_K);
  __half *xf, *qf, *kf, *vf, *yf, *wqf, *wof;
  cudaGetSymbolAddress((void**)&xf, g_xf);
  cudaGetSymbolAddress((void**)&qf, g_Qf);
  cudaGetSymbolAddress((void**)&kf, g_Kf);
  cudaGetSymbolAddress((void**)&vf, g_Vf);
  cudaGetSymbolAddress((void**)&yf, g_Yf);
  cudaGetSymbolAddress((void**)&wqf, g_Wqt_f);
  cudaGetSymbolAddress((void**)&wof, g_Wot_f);
  __nv_bfloat16 *xh, *xl, *ch, *cl, *wch, *wcl, *wkh, *wkl, *wvh, *wvl;
  cudaGetSymbolAddress((void**)&xh, g_xh);
  cudaGetSymbolAddress((void**)&xl, g_xl);
  cudaGetSymbolAddress((void**)&ch, g_ch);
  cudaGetSymbolAddress((void**)&cl, g_cl);
  cudaGetSymbolAddress((void**)&wch, g_Wct_h);
  cudaGetSymbolAddress((void**)&wcl, g_Wct_l);
  cudaGetSymbolAddress((void**)&wkh, g_Wkt_h);
  cudaGetSymbolAddress((void**)&wkl, g_Wkt_l);
  cudaGetSymbolAddress((void**)&wvh, g_Wvt_h);
  cudaGetSymbolAddress((void**)&wvl, g_Wvt_l);

  const int M = B * L;  // 4096

  cudaFuncSetAttribute(mma_gemm, cudaFuncAttributeMaxDynamicSharedMemorySize, GSMEM);
  cudaFuncSetAttribute(mma_gemm_f16, cudaFuncAttributeMaxDynamicSharedMemorySize, GSMEM_F16);
  cudaFuncSetAttribute(attn_mma, cudaFuncAttributeMaxDynamicSharedMemorySize, ASMEM);

  // preprocessing
  split3_kernel<<<(M * HID / 4 + 255) / 256, 256>>>(x, xf, xh, xl, M * HID / 4);
  tsplit_f16_kernel<<<dim3((NH * HDIM) / 32, HID / 32), 256>>>(Wq, wqf, HID, NH * HDIM);
  tsplit_kernel<<<dim3(LAT / 32, HID / 32), 256>>>(Wc, wch, wcl, HID, LAT);
  tsplit_kernel<<<dim3((NKV * HDIM) / 32, LAT / 32), 256>>>(Wk, wkh, wkl, LAT, NKV * HDIM);
  tsplit_kernel<<<dim3((NKV * HDIM) / 32, LAT / 32), 256>>>(Wv, wvh, wvl, LAT, NKV * HDIM);
  tsplit_f16_kernel<<<dim3(HID / 32, (NH * HDIM) / 32), 256>>>(Wo, wof, NH * HDIM, HID);

  // projections
  mma_gemm_f16<<<dim3((NH * HDIM) / BN, M / BM), 256, GSMEM_F16>>>(
      xf, wqf, Qp, M, NH * HDIM, HID);
  mma_gemm<<<dim3(LAT / BN, M / BM), 256, GSMEM>>>(
      xh, xl, wch, wcl, nullptr, ch, cl, nullptr, M, LAT, HID, 1);
  mma_gemm<<<dim3((NKV * HDIM) / BN, M / BM), 256, GSMEM>>>(
      ch, cl, wkh, wkl, Kp, nullptr, nullptr, nullptr, M, NKV * HDIM, LAT, 0);
  mma_gemm<<<dim3((NKV * HDIM) / BN, M / BM), 256, GSMEM>>>(
      ch, cl, wvh, wvl, nullptr, nullptr, nullptr, vf, M, NKV * HDIM, LAT, 2);

  // RoPE -> fp16
  const int totQ = B * L * NH * 64;
  rope_f16_kernel<<<(totQ + 255) / 256, 256>>>(Qp, qf, NH, totQ);
  const int totK = B * L * NKV * 64;
  rope_f16_kernel<<<(totK + 255) / 256, 256>>>(Kp, kf, NKV, totK);

  // attention
  attn_mma<<<dim3(L / AQ, NH, B), 256, ASMEM>>>(qf, kf, vf, mask, yf);

  // output projection
  mma_gemm_f16<<<dim3(HID / BN, M / BM), 256, GSMEM_F16>>>(
      yf, wof, out, M, HID, HID);
}

// round 6
// speedup vs baseline: 4.5561x; 1.1075x over previous
#include <cuda_runtime.h>
#include <cuda_fp16.h>
#include <cstdint>
#include <math.h>

#define B 2
#define L 2048
#define HID 2048
#define NH 16
#define NKV 4
#define HDIM 128
#define LAT 512
#define SCALE 0.08838834764831845f /* 1/sqrt(128) */

// ======================= helpers =======================
__device__ __forceinline__ uint32_t smem_to_u32(const void* p) {
  uint32_t a;
  asm("{ .reg .u64 t; cvta.to.shared.u64 t, %1; cvt.u32.u64 %0, t; }"
      : "=r"(a) : "l"(p));
  return a;
}
__device__ __forceinline__ void cp16(uint32_t dst, const void* src) {
  asm volatile("cp.async.cg.shared.global [%0], [%1], 16;" ::"r"(dst), "l"(src));
}
#define CP_COMMIT() asm volatile("cp.async.commit_group;" ::: "memory")
#define CP_WAIT1() asm volatile("cp.async.wait_group 1;" ::: "memory")
#define CP_WAIT0() asm volatile("cp.async.wait_group 0;" ::: "memory")

__device__ __forceinline__ void ldsm4(uint32_t addr, uint32_t* r) {
  asm volatile("ldmatrix.sync.aligned.m8n8.x4.shared.b16 {%0,%1,%2,%3}, [%4];"
               : "=r"(r[0]), "=r"(r[1]), "=r"(r[2]), "=r"(r[3]) : "r"(addr));
}
__device__ __forceinline__ void ldsm4t(uint32_t addr, uint32_t* r) {
  asm volatile(
      "ldmatrix.sync.aligned.m8n8.x4.trans.shared.b16 {%0,%1,%2,%3}, [%4];"
      : "=r"(r[0]), "=r"(r[1]), "=r"(r[2]), "=r"(r[3]) : "r"(addr));
}
__device__ __forceinline__ void mma16816h(float* c, const uint32_t* a,
                                          const uint32_t* b) {
  asm volatile(
      "mma.sync.aligned.m16n8k16.row.col.f32.f16.f16.f32 "
      "{%0,%1,%2,%3}, {%4,%5,%6,%7}, {%8,%9}, {%0,%1,%2,%3};"
      : "+f"(c[0]), "+f"(c[1]), "+f"(c[2]), "+f"(c[3])
      : "r"(a[0]), "r"(a[1]), "r"(a[2]), "r"(a[3]), "r"(b[0]), "r"(b[1]));
}
__device__ __forceinline__ uint32_t pk2h(float lo, float hi) {
  __half2 h = __floats2half2_rn(lo, hi);
  return *(uint32_t*)&h;
}

// ======================= scratch =======================
__device__ float g_Q[(size_t)B * L * NH * HDIM];
__device__ float g_K[(size_t)B * L * NKV * HDIM];

__device__ __half g_xf[(size_t)B * L * HID];
__device__ __half g_cf[(size_t)B * L * LAT];
__device__ __half g_Qf[(size_t)B * L * NH * HDIM];
__device__ __half g_Kf[(size_t)B * L * NKV * HDIM];
__device__ __half g_Vf[(size_t)B * L * NKV * HDIM];
__device__ __half g_Yf[(size_t)B * L * HID];
__device__ __half g_Wqt_f[(size_t)NH * HDIM * HID];
__device__ __half g_Wct_f[(size_t)LAT * HID];
__device__ __half g_Wkt_f[(size_t)NKV * HDIM * LAT];
__device__ __half g_Wvt_f[(size_t)NKV * HDIM * LAT];
__device__ __half g_Wot_f[(size_t)HID * NH * HDIM];

// ======================= preprocessing =======================
// fp32 -> fp16 (vectorized by 4)
__global__ void split_f16_kernel(const float* __restrict__ s,
                                 __half* __restrict__ f, int n4) {
  int i = blockIdx.x * blockDim.x + threadIdx.x;
  if (i >= n4) return;
  float4 v = ((const float4*)s)[i];
  ((__half2*)f)[2 * i] = __floats2half2_rn(v.x, v.y);
  ((__half2*)f)[2 * i + 1] = __floats2half2_rn(v.z, v.w);
}

// W[K,N] fp32 -> Wt[N,K] fp16
__global__ __launch_bounds__(256) void tsplit_f16_kernel(
    const float* __restrict__ W, __half* __restrict__ f, int K, int N) {
  __shared__ float t[32][33];
  const int n0 = blockIdx.x * 32, k0 = blockIdx.y * 32;
  const int tx = threadIdx.x & 31, ty = threadIdx.x >> 5;
#pragma unroll
  for (int i = 0; i < 32; i += 8)
    t[ty + i][tx] = W[(size_t)(k0 + ty + i) * N + n0 + tx];
  __syncthreads();
#pragma unroll
  for (int i = 0; i < 32; i += 8)
    f[(size_t)(n0 + ty + i) * K + k0 + tx] = __float2half(t[tx][ty + i]);
}

// RoPE fp32 -> fp16, layout [B, L, H, 128]
__global__ void rope_f16_kernel(const float* __restrict__ t,
                                __half* __restrict__ f, int H, int total) {
  int i = blockIdx.x * blockDim.x + threadIdx.x;
  if (i >= total) return;
  const int hf = i & 63;
  const int h = (i >> 6) % H;
  const int bl = i / (64 * H);
  const int l = bl & (L - 1);
  const double inv = exp(-(double)hf * 0.14391156831212788);
  const double fr = (double)l * inv;
  const float c = (float)cos(fr);
  const float s = (float)sin(fr);
  const size_t base = ((size_t)bl * H + h) * HDIM;
  const float a = t[base + hf];
  const float b2 = t[base + hf + 64];
  f[base + hf] = __float2half(a * c - b2 * s);
  f[base + hf + 64] = __float2half(b2 * c + a * s);
}

// ======================= single-pass fp16 GEMM =======================
// C[M,N] = A[M,K] @ B[N,K]^T, fp16 in, fp32 accum. BK=64, XOR-swizzled rows.
// mode 0: fp32 out, mode 1: fp16 out.
#define BM 128
#define BN 128
#define FBK 64
#define FTILEB 16384u
#define FSTAGEB 32768u
#define GSMEM_F16 65536

__global__ __launch_bounds__(256) void mma_gemm_f16(
    const __half* __restrict__ A, const __half* __restrict__ Bm,
    float* __restrict__ C, __half* __restrict__ C16, int M, int N, int K,
    int mode) {
  extern __shared__ char smem[];
  const uint32_t sb = smem_to_u32(smem);
  const int tid = threadIdx.x, wid = tid >> 5, lane = tid & 31;
  const int wm = wid >> 2, wn = wid & 3;
  const int m0 = blockIdx.y * BM, n0 = blockIdx.x * BN;
  const __half* pA = A + (size_t)m0 * K;
  const __half* pB = Bm + (size_t)n0 * K;

  float acc[4][4][4];
#pragma unroll
  for (int f = 0; f < 4; f++)
#pragma unroll
    for (int n = 0; n < 4; n++)
#pragma unroll
      for (int e = 0; e < 4; e++) acc[f][n][e] = 0.f;

  auto load_stage = [&](int k0, int buf) {
    const uint32_t base = sb + buf * FSTAGEB;
#pragma unroll
    for (int i = 0; i < 4; i++) {
      const int idx = i * 256 + tid;
      const int r = idx >> 3, c = idx & 7;
      const uint32_t d = base + r * 128u + ((uint32_t)(c ^ (r & 7)) << 4);
      const size_t go = (size_t)r * K + k0 + c * 8;
      cp16(d, pA + go);
      cp16(d + FTILEB, pB + go);
    }
    CP_COMMIT();
  };

  const int S = K / FBK;
  load_stage(0, 0);
  load_stage(FBK, 1);

  const int rowa = wm * 64 + (lane & 15);
  const int rowb = wn * 32 + (lane & 7) + ((lane >> 4) << 3);

  for (int s = 0; s < S; s++) {
    const int buf = s & 1;
    if (s == S - 1) CP_WAIT0(); else CP_WAIT1();
    __syncthreads();
    const uint32_t abase = sb + buf * FSTAGEB;
    const uint32_t bbase = abase + FTILEB;
#pragma unroll
    for (int ks = 0; ks < 4; ks++) {
      uint32_t ah[4][4], bh[2][4];
      const int ca = 2 * ks + (lane >> 4);
      const int cb = 2 * ks + ((lane >> 3) & 1);
#pragma unroll
      for (int f = 0; f < 4; f++) {
        const int rr = rowa + f * 16;
        ldsm4(abase + rr * 128u + ((uint32_t)(ca ^ (rr & 7)) << 4), ah[f]);
      }
#pragma unroll
      for (int p = 0; p < 2; p++) {
        const int rr = rowb + p * 16;
        ldsm4(bbase + rr * 128u + ((uint32_t)(cb ^ (rr & 7)) << 4), bh[p]);
      }
#pragma unroll
      for (int f = 0; f < 4; f++)
#pragma unroll
        for (int n = 0; n < 4; n++)
          mma16816h(acc[f][n], ah[f], &bh[n >> 1][(n & 1) * 2]);
    }
    __syncthreads();
    if (s + 2 < S) load_stage((s + 2) * FBK, buf);
  }

#pragma unroll
  for (int f = 0; f < 4; f++) {
    const int row = m0 + wm * 64 + f * 16 + (lane >> 2);
#pragma unroll
    for (int n = 0; n < 4; n++) {
      const int col = n0 + wn * 32 + n * 8 + (lane & 3) * 2;
      if (mode == 0) {
        *(float2*)&C[(size_t)row * N + col] =
            make_float2(acc[f][n][0], acc[f][n][1]);
        *(float2*)&C[(size_t)(row + 8) * N + col] =
            make_float2(acc[f][n][2], acc[f][n][3]);
      } else {
        *(__half2*)&C16[(size_t)row * N + col] =
            __floats2half2_rn(acc[f][n][0], acc[f][n][1]);
        *(__half2*)&C16[(size_t)(row + 8) * N + col] =
            __floats2half2_rn(acc[f][n][2], acc[f][n][3]);
      }
    }
  }
}

// ======================= fp16 flash attention =======================
// 128 q-rows per block, 32-key tiles, 8 warps (warp = 16 q rows).
#define AQ 128
#define AKT 32
#define ASMEM 32768

__global__ __launch_bounds__(256) void attn_mma(
    const __half* __restrict__ Qf, const __half* __restrict__ Kf,
    const __half* __restrict__ Vf, const int* __restrict__ mask,
    __half* __restrict__ Yf) {
  extern __shared__ char smem[];
  const uint32_t sb = smem_to_u32(smem);
  // heavy (large qt) blocks first for load balance
  const int qt = gridDim.x - 1 - blockIdx.x;
  const int h = blockIdx.y, b = blockIdx.z;
  const int hkv = h >> 2;
  const int tid = threadIdx.x, w = tid >> 5, lane = tid & 31;
  const int q0 = qt * AQ;

  // ---- stage Q through smem, extract register fragments ----
  {
    const __half* qg = Qf + ((size_t)(b * L + q0) * NH + h) * 128;
#pragma unroll
    for (int i = 0; i < 8; i++) {
      const int idx = i * 256 + tid;
      const int r = idx >> 4, c = idx & 15;
      const uint32_t d = sb + r * 256u + ((uint32_t)(c ^ (r & 7)) << 4);
      cp16(d, qg + (size_t)r * (NH * 128) + c * 8);
    }
    CP_COMMIT();
    CP_WAIT0();
    __syncthreads();
  }
  uint32_t qh[8][4];
  {
    const int rowa = w * 16 + (lane & 15);
#pragma unroll
    for (int kd = 0; kd < 8; kd++) {
      const int ca = 2 * kd + (lane >> 4);
      ldsm4(sb + rowa * 256u + ((uint32_t)(ca ^ (rowa & 7)) << 4), qh[kd]);
    }
  }
  __syncthreads();  // Q smem free for KV buffers

  float o[16][4];
#pragma unroll
  for (int nf = 0; nf < 16; nf++)
#pragma unroll
    for (int e = 0; e < 4; e++) o[nf][e] = 0.f;
  float m2[2] = {-1e30f, -1e30f}, ls[2] = {0.f, 0.f};

  const __half* khg = Kf + ((size_t)(b * L) * NKV + hkv) * 128;
  const __half* vhg = Vf + ((size_t)(b * L) * NKV + hkv) * 128;
  const int* mrow = mask + b * L;

  auto load_kv = [&](int t, int buf) {
    const int k0 = t * AKT;
    const uint32_t base = sb + buf * 16384u;
#pragma unroll
    for (int i = 0; i < 2; i++) {
      const int idx = i * 256 + tid;
      const int r = idx >> 4, c = idx & 15;
      const uint32_t d = base + r * 256u + ((uint32_t)(c ^ (r & 7)) << 4);
      const size_t go = (size_t)(k0 + r) * (NKV * 128) + c * 8;
      cp16(d, khg + go);
      cp16(d + 8192u, vhg + go);
    }
    CP_COMMIT();
  };

  const int nkt = qt * 4 + 4;
  load_kv(0, 0);
  load_kv(1, 1);

  const int qa = q0 + w * 16 + (lane >> 2);
  const int qb = qa + 8;
  const int rbB = (lane & 7) + ((lane >> 4) << 3);
  const int rvB = (lane & 7) + (((lane >> 3) & 1) << 3);

  for (int kt = 0; kt < nkt; kt++) {
    const int buf = kt & 1;
    const int k0 = kt * AKT;
    if (kt == nkt - 1) CP_WAIT0(); else CP_WAIT1();
    __syncthreads();

    if (k0 <= q0 + w * 16 + 15) {
      const uint32_t kb = sb + buf * 16384u;
      float s[4][4];
#pragma unroll
      for (int n = 0; n < 4; n++)
#pragma unroll
        for (int e = 0; e < 4; e++) s[n][e] = 0.f;

      // S = Q K^T (fp16, fp32 accum)
#pragma unroll
      for (int kd = 0; kd < 8; kd++) {
        const int cb = 2 * kd + ((lane >> 3) & 1);
        const uint32_t b0a =
            kb + (uint32_t)rbB * 256u + ((uint32_t)(cb ^ (rbB & 7)) << 4);
        uint32_t bh0[4], bh1[4];
        ldsm4(b0a, bh0);
        ldsm4(b0a + 16u * 256u, bh1);
#pragma unroll
        for (int n = 0; n < 4; n++) {
          const uint32_t* bp = (n < 2) ? &bh0[(n & 1) * 2] : &bh1[(n & 1) * 2];
          mma16816h(s[n], qh[kd], bp);
        }
      }

      // masked scale + row maxes
      float rmax[2] = {-1e30f, -1e30f};
#pragma unroll
      for (int n = 0; n < 4; n++) {
        const int col = k0 + n * 8 + (lane & 3) * 2;
        const bool mk0 = mrow[col] > 0, mk1 = mrow[col + 1] > 0;
        s[n][0] = (mk0 && col <= qa) ? s[n][0] * SCALE : -1e30f;
        s[n][1] = (mk1 && col + 1 <= qa) ? s[n][1] * SCALE : -1e30f;
        s[n][2] = (mk0 && col <= qb) ? s[n][2] * SCALE : -1e30f;
        s[n][3] = (mk1 && col + 1 <= qb) ? s[n][3] * SCALE : -1e30f;
        rmax[0] = fmaxf(rmax[0], fmaxf(s[n][0], s[n][1]));
        rmax[1] = fmaxf(rmax[1], fmaxf(s[n][2], s[n][3]));
      }
#pragma unroll
      for (int off = 1; off <= 2; off <<= 1) {
        rmax[0] = fmaxf(rmax[0], __shfl_xor_sync(0xffffffffu, rmax[0], off));
        rmax[1] = fmaxf(rmax[1], __shfl_xor_sync(0xffffffffu, rmax[1], off));
      }
      const float mn0 = fmaxf(m2[0], rmax[0]);
      const float mn1 = fmaxf(m2[1], rmax[1]);
      const float al0 = __expf(m2[0] - mn0);
      const float al1 = __expf(m2[1] - mn1);
      m2[0] = mn0;
      m2[1] = mn1;
      float ps0 = 0.f, ps1 = 0.f;
#pragma unroll
      for (int n = 0; n < 4; n++) {
        s[n][0] = __expf(s[n][0] - mn0);
        s[n][1] = __expf(s[n][1] - mn0);
        s[n][2] = __expf(s[n][2] - mn1);
        s[n][3] = __expf(s[n][3] - mn1);
        ps0 += s[n][0] + s[n][1];
        ps1 += s[n][2] + s[n][3];
      }
#pragma unroll
      for (int off = 1; off <= 2; off <<= 1) {
        ps0 += __shfl_xor_sync(0xffffffffu, ps0, off);
        ps1 += __shfl_xor_sync(0xffffffffu, ps1, off);
      }
      ls[0] = ls[0] * al0 + ps0;
      ls[1] = ls[1] * al1 + ps1;
#pragma unroll
      for (int nf = 0; nf < 16; nf++) {
        o[nf][0] *= al0;
        o[nf][1] *= al0;
        o[nf][2] *= al1;
        o[nf][3] *= al1;
      }

      // pack P -> fp16 A fragments
      uint32_t pa[2][4];
#pragma unroll
      for (int ks = 0; ks < 2; ks++) {
        pa[ks][0] = pk2h(s[2 * ks][0], s[2 * ks][1]);
        pa[ks][1] = pk2h(s[2 * ks][2], s[2 * ks][3]);
        pa[ks][2] = pk2h(s[2 * ks + 1][0], s[2 * ks + 1][1]);
        pa[ks][3] = pk2h(s[2 * ks + 1][2], s[2 * ks + 1][3]);
      }

      // O += P V
      const uint32_t vb = kb + 8192u;
#pragma unroll
      for (int ks = 0; ks < 2; ks++) {
        const int rowv = 16 * ks + rvB;
#pragma unroll
        for (int j = 0; j < 8; j++) {
          const int cv = 2 * j + (lane >> 4);
          uint32_t vhf[4];
          ldsm4t(vb + (uint32_t)rowv * 256u +
                     ((uint32_t)(cv ^ (rowv & 7)) << 4),
                 vhf);
          mma16816h(o[2 * j], pa[ks], &vhf[0]);
          mma16816h(o[2 * j + 1], pa[ks], &vhf[2]);
        }
      }
    }

    __syncthreads();
    if (kt + 2 < nkt) load_kv(kt + 2, buf);
  }

  // ---- normalize + write fp16 Y ----
  const float inv0 = 1.f / ls[0], inv1 = 1.f / ls[1];
  const size_t rA = (size_t)(b * L + qa) * (size_t)HID + h * 128;
  const size_t rB = rA + (size_t)8 * HID;
#pragma unroll
  for (int nf = 0; nf < 16; nf++) {
    const int d = nf * 8 + (lane & 3) * 2;
    *(__half2*)&Yf[rA + d] = __floats2half2_rn(o[nf][0] * inv0, o[nf][1] * inv0);
    *(__half2*)&Yf[rB + d] = __floats2half2_rn(o[nf][2] * inv1, o[nf][3] * inv1);
  }
}

// ======================= launch =======================
extern "C" void kernel_launch(void* const* d_in, const int* in_sizes, int n_in,
                              void* d_out, int out_size) {
  const float* x = (const float*)d_in[0];
  const float* Wq = (const float*)d_in[1];
  const float* Wc = (const float*)d_in[2];
  const float* Wk = (const float*)d_in[3];
  const float* Wv = (const float*)d_in[4];
  const float* Wo = (const float*)d_in[5];
  const int* mask = (const int*)d_in[6];
  float* out = (float*)d_out;

  float *Qp, *Kp;
  cudaGetSymbolAddress((void**)&Qp, g_Q);
  cudaGetSymbolAddress((void**)&Kp, g_K);
  __half *xf, *cf, *qf, *kf, *vf, *yf, *wqf, *wcf, *wkf, *wvf, *wof;
  cudaGetSymbolAddress((void**)&xf, g_xf);
  cudaGetSymbolAddress((void**)&cf, g_cf);
  cudaGetSymbolAddress((void**)&qf, g_Qf);
  cudaGetSymbolAddress((void**)&kf, g_Kf);
  cudaGetSymbolAddress((void**)&vf, g_Vf);
  cudaGetSymbolAddress((void**)&yf, g_Yf);
  cudaGetSymbolAddress((void**)&wqf, g_Wqt_f);
  cudaGetSymbolAddress((void**)&wcf, g_Wct_f);
  cudaGetSymbolAddress((void**)&wkf, g_Wkt_f);
  cudaGetSymbolAddress((void**)&wvf, g_Wvt_f);
  cudaGetSymbolAddress((void**)&wof, g_Wot_f);

  const int M = B * L;  // 4096

  cudaFuncSetAttribute(mma_gemm_f16, cudaFuncAttributeMaxDynamicSharedMemorySize,
                       GSMEM_F16);
  cudaFuncSetAttribute(attn_mma, cudaFuncAttributeMaxDynamicSharedMemorySize,
                       ASMEM);

  // preprocessing (ordered so launch index 5 == Wq GEMM for ncu -s 5)
  split_f16_kernel<<<(M * HID / 4 + 255) / 256, 256>>>(x, xf, M * HID / 4);        // 0
  tsplit_f16_kernel<<<dim3((NH * HDIM) / 32, HID / 32), 256>>>(Wq, wqf, HID, NH * HDIM);  // 1
  tsplit_f16_kernel<<<dim3(LAT / 32, HID / 32), 256>>>(Wc, wcf, HID, LAT);         // 2
  tsplit_f16_kernel<<<dim3((NKV * HDIM) / 32, LAT / 32), 256>>>(Wk, wkf, LAT, NKV * HDIM);  // 3
  tsplit_f16_kernel<<<dim3((NKV * HDIM) / 32, LAT / 32), 256>>>(Wv, wvf, LAT, NKV * HDIM);  // 4

  // projections
  mma_gemm_f16<<<dim3((NH * HDIM) / BN, M / BM), 256, GSMEM_F16>>>(
      xf, wqf, Qp, nullptr, M, NH * HDIM, HID, 0);                                  // 5 <- ncu
  mma_gemm_f16<<<dim3(LAT / BN, M / BM), 256, GSMEM_F16>>>(
      xf, wcf, nullptr, cf, M, LAT, HID, 1);                                        // 6
  mma_gemm_f16<<<dim3((NKV * HDIM) / BN, M / BM), 256, GSMEM_F16>>>(
      cf, wkf, Kp, nullptr, M, NKV * HDIM, LAT, 0);                                 // 7
  mma_gemm_f16<<<dim3((NKV * HDIM) / BN, M / BM), 256, GSMEM_F16>>>(
      cf, wvf, nullptr, vf, M, NKV * HDIM, LAT, 1);                                 // 8

  tsplit_f16_kernel<<<dim3(HID / 32, (NH * HDIM) / 32), 256>>>(Wo, wof, NH * HDIM, HID);  // 9

  // RoPE -> fp16
  const int totQ = B * L * NH * 64;
  rope_f16_kernel<<<(totQ + 255) / 256, 256>>>(Qp, qf, NH, totQ);                   // 10
  const int totK = B * L * NKV * 64;
  rope_f16_kernel<<<(totK + 255) / 256, 256>>>(Kp, kf, NKV, totK);                  // 11

  // attention
  attn_mma<<<dim3(L / AQ, NH, B), 256, ASMEM>>>(qf, kf, vf, mask, yf);              // 12

  // output projection
  mma_gemm_f16<<<dim3(HID / BN, M / BM), 256, GSMEM_F16>>>(
      yf, wof, out, nullptr, M, HID, HID, 0);                                       // 13
}

// round 7
// speedup vs baseline: 4.6743x; 1.0260x over previous
#include <cuda_runtime.h>
#include <cuda_fp16.h>
#include <cstdint>
#include <math.h>

#define B 2
#define L 2048
#define HID 2048
#define NH 16
#define NKV 4
#define HDIM 128
#define LAT 512
#define SCALE 0.08838834764831845f /* 1/sqrt(128) */

// ======================= helpers =======================
__device__ __forceinline__ uint32_t smem_to_u32(const void* p) {
  uint32_t a;
  asm("{ .reg .u64 t; cvta.to.shared.u64 t, %1; cvt.u32.u64 %0, t; }"
      : "=r"(a) : "l"(p));
  return a;
}
__device__ __forceinline__ void cp16(uint32_t dst, const void* src) {
  asm volatile("cp.async.cg.shared.global [%0], [%1], 16;" ::"r"(dst), "l"(src));
}
#define CP_COMMIT() asm volatile("cp.async.commit_group;" ::: "memory")
#define CP_WAIT1() asm volatile("cp.async.wait_group 1;" ::: "memory")
#define CP_WAIT0() asm volatile("cp.async.wait_group 0;" ::: "memory")

__device__ __forceinline__ void ldsm4(uint32_t addr, uint32_t* r) {
  asm volatile("ldmatrix.sync.aligned.m8n8.x4.shared.b16 {%0,%1,%2,%3}, [%4];"
               : "=r"(r[0]), "=r"(r[1]), "=r"(r[2]), "=r"(r[3]) : "r"(addr));
}
__device__ __forceinline__ void ldsm4t(uint32_t addr, uint32_t* r) {
  asm volatile(
      "ldmatrix.sync.aligned.m8n8.x4.trans.shared.b16 {%0,%1,%2,%3}, [%4];"
      : "=r"(r[0]), "=r"(r[1]), "=r"(r[2]), "=r"(r[3]) : "r"(addr));
}
__device__ __forceinline__ void mma16816h(float* c, const uint32_t* a,
                                          const uint32_t* b) {
  asm volatile(
      "mma.sync.aligned.m16n8k16.row.col.f32.f16.f16.f32 "
      "{%0,%1,%2,%3}, {%4,%5,%6,%7}, {%8,%9}, {%0,%1,%2,%3};"
      : "+f"(c[0]), "+f"(c[1]), "+f"(c[2]), "+f"(c[3])
      : "r"(a[0]), "r"(a[1]), "r"(a[2]), "r"(a[3]), "r"(b[0]), "r"(b[1]));
}
__device__ __forceinline__ uint32_t pk2h(float lo, float hi) {
  __half2 h = __floats2half2_rn(lo, hi);
  return *(uint32_t*)&h;
}

// ======================= scratch =======================
__device__ float g_Q[(size_t)B * L * NH * HDIM];
__device__ float g_K[(size_t)B * L * NKV * HDIM];

__device__ __half g_xf[(size_t)B * L * HID];
__device__ __half g_cf[(size_t)B * L * LAT];
__device__ __half g_Qf[(size_t)B * L * NH * HDIM];
__device__ __half g_Kf[(size_t)B * L * NKV * HDIM];
__device__ __half g_Vf[(size_t)B * L * NKV * HDIM];
__device__ __half g_Yf[(size_t)B * L * HID];
__device__ __half g_Wqt_f[(size_t)NH * HDIM * HID];
__device__ __half g_Wct_f[(size_t)LAT * HID];
__device__ __half g_Wkvt_f[(size_t)2 * NKV * HDIM * LAT];  // [Wk; Wv] rows
__device__ __half g_Wot_f[(size_t)HID * NH * HDIM];

// ======================= stream context (created pre-main) ==============
namespace {
struct Ctx {
  cudaStream_t side;
  cudaEvent_t e0, e1;
  Ctx() {
    cudaStreamCreateWithFlags(&side, cudaStreamNonBlocking);
    cudaEventCreateWithFlags(&e0, cudaEventDisableTiming);
    cudaEventCreateWithFlags(&e1, cudaEventDisableTiming);
  }
};
Ctx g_ctx;
}  // namespace

// ======================= preprocessing =======================
__global__ void split_f16_kernel(const float* __restrict__ s,
                                 __half* __restrict__ f, int n4) {
  int i = blockIdx.x * blockDim.x + threadIdx.x;
  if (i >= n4) return;
  float4 v = ((const float4*)s)[i];
  ((__half2*)f)[2 * i] = __floats2half2_rn(v.x, v.y);
  ((__half2*)f)[2 * i + 1] = __floats2half2_rn(v.z, v.w);
}

// W[K,N] fp32 -> Wt[N,K] fp16
__global__ __launch_bounds__(256) void tsplit_f16_kernel(
    const float* __restrict__ W, __half* __restrict__ f, int K, int N) {
  __shared__ float t[32][33];
  const int n0 = blockIdx.x * 32, k0 = blockIdx.y * 32;
  const int tx = threadIdx.x & 31, ty = threadIdx.x >> 5;
#pragma unroll
  for (int i = 0; i < 32; i += 8)
    t[ty + i][tx] = W[(size_t)(k0 + ty + i) * N + n0 + tx];
  __syncthreads();
#pragma unroll
  for (int i = 0; i < 32; i += 8)
    f[(size_t)(n0 + ty + i) * K + k0 + tx] = __float2half(t[tx][ty + i]);
}

// RoPE fp32 -> fp16, layout [B, L, H, 128]
__global__ void rope_f16_kernel(const float* __restrict__ t,
                                __half* __restrict__ f, int H, int total) {
  int i = blockIdx.x * blockDim.x + threadIdx.x;
  if (i >= total) return;
  const int hf = i & 63;
  const int h = (i >> 6) % H;
  const int bl = i / (64 * H);
  const int l = bl & (L - 1);
  const double inv = exp(-(double)hf * 0.14391156831212788);
  const double fr = (double)l * inv;
  const float c = (float)cos(fr);
  const float s = (float)sin(fr);
  const size_t base = ((size_t)bl * H + h) * HDIM;
  const float a = t[base + hf];
  const float b2 = t[base + hf + 64];
  f[base + hf] = __float2half(a * c - b2 * s);
  f[base + hf + 64] = __float2half(b2 * c + a * s);
}

// ======================= single-pass fp16 GEMM =======================
// C[M,N] = A[M,K] @ B[N,K]^T, fp16 in, fp32 accum. BK=64, XOR-swizzled rows.
// mode 0: fp32 out; mode 1: fp16 out; mode 2: KV split (col<512 -> fp32 C
// with row-stride 512, col>=512 -> fp16 C16 at col-512, row-stride 512).
#define BM 128
#define BN 128
#define FBK 64
#define FTILEB 16384u
#define FSTAGEB 32768u
#define GSMEM_F16 65536

__global__ __launch_bounds__(256) void mma_gemm_f16(
    const __half* __restrict__ A, const __half* __restrict__ Bm,
    float* __restrict__ C, __half* __restrict__ C16, int M, int N, int K,
    int mode) {
  extern __shared__ char smem[];
  const uint32_t sb = smem_to_u32(smem);
  const int tid = threadIdx.x, wid = tid >> 5, lane = tid & 31;
  const int wm = wid >> 2, wn = wid & 3;
  const int m0 = blockIdx.y * BM, n0 = blockIdx.x * BN;
  const __half* pA = A + (size_t)m0 * K;
  const __half* pB = Bm + (size_t)n0 * K;

  float acc[4][4][4];
#pragma unroll
  for (int f = 0; f < 4; f++)
#pragma unroll
    for (int n = 0; n < 4; n++)
#pragma unroll
      for (int e = 0; e < 4; e++) acc[f][n][e] = 0.f;

  auto load_stage = [&](int k0, int buf) {
    const uint32_t base = sb + buf * FSTAGEB;
#pragma unroll
    for (int i = 0; i < 4; i++) {
      const int idx = i * 256 + tid;
      const int r = idx >> 3, c = idx & 7;
      const uint32_t d = base + r * 128u + ((uint32_t)(c ^ (r & 7)) << 4);
      const size_t go = (size_t)r * K + k0 + c * 8;
      cp16(d, pA + go);
      cp16(d + FTILEB, pB + go);
    }
    CP_COMMIT();
  };

  const int S = K / FBK;
  load_stage(0, 0);
  load_stage(FBK, 1);

  const int rowa = wm * 64 + (lane & 15);
  const int rowb = wn * 32 + (lane & 7) + ((lane >> 4) << 3);

  for (int s = 0; s < S; s++) {
    const int buf = s & 1;
    if (s == S - 1) CP_WAIT0(); else CP_WAIT1();
    __syncthreads();
    const uint32_t abase = sb + buf * FSTAGEB;
    const uint32_t bbase = abase + FTILEB;
#pragma unroll
    for (int ks = 0; ks < 4; ks++) {
      uint32_t ah[4][4], bh[2][4];
      const int ca = 2 * ks + (lane >> 4);
      const int cb = 2 * ks + ((lane >> 3) & 1);
#pragma unroll
      for (int f = 0; f < 4; f++) {
        const int rr = rowa + f * 16;
        ldsm4(abase + rr * 128u + ((uint32_t)(ca ^ (rr & 7)) << 4), ah[f]);
      }
#pragma unroll
      for (int p = 0; p < 2; p++) {
        const int rr = rowb + p * 16;
        ldsm4(bbase + rr * 128u + ((uint32_t)(cb ^ (rr & 7)) << 4), bh[p]);
      }
#pragma unroll
      for (int f = 0; f < 4; f++)
#pragma unroll
        for (int n = 0; n < 4; n++)
          mma16816h(acc[f][n], ah[f], &bh[n >> 1][(n & 1) * 2]);
    }
    __syncthreads();
    if (s + 2 < S) load_stage((s + 2) * FBK, buf);
  }

#pragma unroll
  for (int f = 0; f < 4; f++) {
    const int row = m0 + wm * 64 + f * 16 + (lane >> 2);
#pragma unroll
    for (int n = 0; n < 4; n++) {
      const int col = n0 + wn * 32 + n * 8 + (lane & 3) * 2;
      if (mode == 0) {
        *(float2*)&C[(size_t)row * N + col] =
            make_float2(acc[f][n][0], acc[f][n][1]);
        *(float2*)&C[(size_t)(row + 8) * N + col] =
            make_float2(acc[f][n][2], acc[f][n][3]);
      } else if (mode == 1) {
        *(__half2*)&C16[(size_t)row * N + col] =
            __floats2half2_rn(acc[f][n][0], acc[f][n][1]);
        *(__half2*)&C16[(size_t)(row + 8) * N + col] =
            __floats2half2_rn(acc[f][n][2], acc[f][n][3]);
      } else {
        if (col < 512) {  // K -> fp32 (RoPE input), row stride 512
          *(float2*)&C[(size_t)row * 512 + col] =
              make_float2(acc[f][n][0], acc[f][n][1]);
          *(float2*)&C[(size_t)(row + 8) * 512 + col] =
              make_float2(acc[f][n][2], acc[f][n][3]);
        } else {  // V -> fp16, row stride 512
          const int cv = col - 512;
          *(__half2*)&C16[(size_t)row * 512 + cv] =
              __floats2half2_rn(acc[f][n][0], acc[f][n][1]);
          *(__half2*)&C16[(size_t)(row + 8) * 512 + cv] =
              __floats2half2_rn(acc[f][n][2], acc[f][n][3]);
        }
      }
    }
  }
}

// ======================= fp16 flash attention =======================
// 128 q-rows per block, 32-key tiles, 8 warps (warp = 16 q rows).
#define AQ 128
#define AKT 32
#define ASMEM 32768

__global__ __launch_bounds__(256) void attn_mma(
    const __half* __restrict__ Qf, const __half* __restrict__ Kf,
    const __half* __restrict__ Vf, const int* __restrict__ mask,
    __half* __restrict__ Yf) {
  extern __shared__ char smem[];
  const uint32_t sb = smem_to_u32(smem);
  const int qt = gridDim.x - 1 - blockIdx.x;  // heavy blocks first
  const int h = blockIdx.y, b = blockIdx.z;
  const int hkv = h >> 2;
  const int tid = threadIdx.x, w = tid >> 5, lane = tid & 31;
  const int q0 = qt * AQ;

  // ---- stage Q through smem, extract register fragments ----
  {
    const __half* qg = Qf + ((size_t)(b * L + q0) * NH + h) * 128;
#pragma unroll
    for (int i = 0; i < 8; i++) {
      const int idx = i * 256 + tid;
      const int r = idx >> 4, c = idx & 15;
      const uint32_t d = sb + r * 256u + ((uint32_t)(c ^ (r & 7)) << 4);
      cp16(d, qg + (size_t)r * (NH * 128) + c * 8);
    }
    CP_COMMIT();
    CP_WAIT0();
    __syncthreads();
  }
  uint32_t qh[8][4];
  {
    const int rowa = w * 16 + (lane & 15);
#pragma unroll
    for (int kd = 0; kd < 8; kd++) {
      const int ca = 2 * kd + (lane >> 4);
      ldsm4(sb + rowa * 256u + ((uint32_t)(ca ^ (rowa & 7)) << 4), qh[kd]);
    }
  }
  __syncthreads();

  float o[16][4];
#pragma unroll
  for (int nf = 0; nf < 16; nf++)
#pragma unroll
    for (int e = 0; e < 4; e++) o[nf][e] = 0.f;
  float m2[2] = {-1e30f, -1e30f}, ls[2] = {0.f, 0.f};

  const __half* khg = Kf + ((size_t)(b * L) * NKV + hkv) * 128;
  const __half* vhg = Vf + ((size_t)(b * L) * NKV + hkv) * 128;
  const int* mrow = mask + b * L;

  auto load_kv = [&](int t, int buf) {
    const int k0 = t * AKT;
    const uint32_t base = sb + buf * 16384u;
#pragma unroll
    for (int i = 0; i < 2; i++) {
      const int idx = i * 256 + tid;
      const int r = idx >> 4, c = idx & 15;
      const uint32_t d = base + r * 256u + ((uint32_t)(c ^ (r & 7)) << 4);
      const size_t go = (size_t)(k0 + r) * (NKV * 128) + c * 8;
      cp16(d, khg + go);
      cp16(d + 8192u, vhg + go);
    }
    CP_COMMIT();
  };

  const int nkt = qt * 4 + 4;
  load_kv(0, 0);
  load_kv(1, 1);

  const int qa = q0 + w * 16 + (lane >> 2);
  const int qb = qa + 8;
  const int rbB = (lane & 7) + ((lane >> 4) << 3);
  const int rvB = (lane & 7) + (((lane >> 3) & 1) << 3);

  for (int kt = 0; kt < nkt; kt++) {
    const int buf = kt & 1;
    const int k0 = kt * AKT;
    if (kt == nkt - 1) CP_WAIT0(); else CP_WAIT1();
    __syncthreads();

    if (k0 <= q0 + w * 16 + 15) {
      const uint32_t kb = sb + buf * 16384u;
      float s[4][4];
#pragma unroll
      for (int n = 0; n < 4; n++)
#pragma unroll
        for (int e = 0; e < 4; e++) s[n][e] = 0.f;

#pragma unroll
      for (int kd = 0; kd < 8; kd++) {
        const int cb = 2 * kd + ((lane >> 3) & 1);
        const uint32_t b0a =
            kb + (uint32_t)rbB * 256u + ((uint32_t)(cb ^ (rbB & 7)) << 4);
        uint32_t bh0[4], bh1[4];
        ldsm4(b0a, bh0);
        ldsm4(b0a + 16u * 256u, bh1);
#pragma unroll
        for (int n = 0; n < 4; n++) {
          const uint32_t* bp = (n < 2) ? &bh0[(n & 1) * 2] : &bh1[(n & 1) * 2];
          mma16816h(s[n], qh[kd], bp);
        }
      }

      float rmax[2] = {-1e30f, -1e30f};
#pragma unroll
      for (int n = 0; n < 4; n++) {
        const int col = k0 + n * 8 + (lane & 3) * 2;
        const bool mk0 = mrow[col] > 0, mk1 = mrow[col + 1] > 0;
        s[n][0] = (mk0 && col <= qa) ? s[n][0] * SCALE : -1e30f;
        s[n][1] = (mk1 && col + 1 <= qa) ? s[n][1] * SCALE : -1e30f;
        s[n][2] = (mk0 && col <= qb) ? s[n][2] * SCALE : -1e30f;
        s[n][3] = (mk1 && col + 1 <= qb) ? s[n][3] * SCALE : -1e30f;
        rmax[0] = fmaxf(rmax[0], fmaxf(s[n][0], s[n][1]));
        rmax[1] = fmaxf(rmax[1], fmaxf(s[n][2], s[n][3]));
      }
#pragma unroll
      for (int off = 1; off <= 2; off <<= 1) {
        rmax[0] = fmaxf(rmax[0], __shfl_xor_sync(0xffffffffu, rmax[0], off));
        rmax[1] = fmaxf(rmax[1], __shfl_xor_sync(0xffffffffu, rmax[1], off));
      }
      const float mn0 = fmaxf(m2[0], rmax[0]);
      const float mn1 = fmaxf(m2[1], rmax[1]);
      const float al0 = __expf(m2[0] - mn0);
      const float al1 = __expf(m2[1] - mn1);
      m2[0] = mn0;
      m2[1] = mn1;
      float ps0 = 0.f, ps1 = 0.f;
#pragma unroll
      for (int n = 0; n < 4; n++) {
        s[n][0] = __expf(s[n][0] - mn0);
        s[n][1] = __expf(s[n][1] - mn0);
        s[n][2] = __expf(s[n][2] - mn1);
        s[n][3] = __expf(s[n][3] - mn1);
        ps0 += s[n][0] + s[n][1];
        ps1 += s[n][2] + s[n][3];
      }
#pragma unroll
      for (int off = 1; off <= 2; off <<= 1) {
        ps0 += __shfl_xor_sync(0xffffffffu, ps0, off);
        ps1 += __shfl_xor_sync(0xffffffffu, ps1, off);
      }
      ls[0] = ls[0] * al0 + ps0;
      ls[1] = ls[1] * al1 + ps1;
#pragma unroll
      for (int nf = 0; nf < 16; nf++) {
        o[nf][0] *= al0;
        o[nf][1] *= al0;
        o[nf][2] *= al1;
        o[nf][3] *= al1;
      }

      uint32_t pa[2][4];
#pragma unroll
      for (int ks = 0; ks < 2; ks++) {
        pa[ks][0] = pk2h(s[2 * ks][0], s[2 * ks][1]);
        pa[ks][1] = pk2h(s[2 * ks][2], s[2 * ks][3]);
        pa[ks][2] = pk2h(s[2 * ks + 1][0], s[2 * ks + 1][1]);
        pa[ks][3] = pk2h(s[2 * ks + 1][2], s[2 * ks + 1][3]);
      }

      const uint32_t vb = kb + 8192u;
#pragma unroll
      for (int ks = 0; ks < 2; ks++) {
        const int rowv = 16 * ks + rvB;
#pragma unroll
        for (int j = 0; j < 8; j++) {
          const int cv = 2 * j + (lane >> 4);
          uint32_t vhf[4];
          ldsm4t(vb + (uint32_t)rowv * 256u +
                     ((uint32_t)(cv ^ (rowv & 7)) << 4),
                 vhf);
          mma16816h(o[2 * j], pa[ks], &vhf[0]);
          mma16816h(o[2 * j + 1], pa[ks], &vhf[2]);
        }
      }
    }

    __syncthreads();
    if (kt + 2 < nkt) load_kv(kt + 2, buf);
  }

  const float inv0 = 1.f / ls[0], inv1 = 1.f / ls[1];
  const size_t rA = (size_t)(b * L + qa) * (size_t)HID + h * 128;
  const size_t rB = rA + (size_t)8 * HID;
#pragma unroll
  for (int nf = 0; nf < 16; nf++) {
    const int d = nf * 8 + (lane & 3) * 2;
    *(__half2*)&Yf[rA + d] = __floats2half2_rn(o[nf][0] * inv0, o[nf][1] * inv0);
    *(__half2*)&Yf[rB + d] = __floats2half2_rn(o[nf][2] * inv1, o[nf][3] * inv1);
  }
}

// ======================= launch =======================
extern "C" void kernel_launch(void* const* d_in, const int* in_sizes, int n_in,
                              void* d_out, int out_size) {
  const float* x = (const float*)d_in[0];
  const float* Wq = (const float*)d_in[1];
  const float* Wc = (const float*)d_in[2];
  const float* Wk = (const float*)d_in[3];
  const float* Wv = (const float*)d_in[4];
  const float* Wo = (const float*)d_in[5];
  const int* mask = (const int*)d_in[6];
  float* out = (float*)d_out;

  float *Qp, *Kp;
  cudaGetSymbolAddress((void**)&Qp, g_Q);
  cudaGetSymbolAddress((void**)&Kp, g_K);
  __half *xf, *cf, *qf, *kf, *vf, *yf, *wqf, *wcf, *wkvf, *wof;
  cudaGetSymbolAddress((void**)&xf, g_xf);
  cudaGetSymbolAddress((void**)&cf, g_cf);
  cudaGetSymbolAddress((void**)&qf, g_Qf);
  cudaGetSymbolAddress((void**)&kf, g_Kf);
  cudaGetSymbolAddress((void**)&vf, g_Vf);
  cudaGetSymbolAddress((void**)&yf, g_Yf);
  cudaGetSymbolAddress((void**)&wqf, g_Wqt_f);
  cudaGetSymbolAddress((void**)&wcf, g_Wct_f);
  cudaGetSymbolAddress((void**)&wkvf, g_Wkvt_f);
  cudaGetSymbolAddress((void**)&wof, g_Wot_f);

  const int M = B * L;  // 4096

  cudaFuncSetAttribute(mma_gemm_f16, cudaFuncAttributeMaxDynamicSharedMemorySize,
                       GSMEM_F16);
  cudaFuncSetAttribute(attn_mma, cudaFuncAttributeMaxDynamicSharedMemorySize,
                       ASMEM);

  // ---- main stream: shared preprocessing ----
  split_f16_kernel<<<(M * HID / 4 + 255) / 256, 256>>>(x, xf, M * HID / 4);  // 0
  tsplit_f16_kernel<<<dim3((NH * HDIM) / 32, HID / 32), 256>>>(
      Wq, wqf, HID, NH * HDIM);                                              // 1
  tsplit_f16_kernel<<<dim3(LAT / 32, HID / 32), 256>>>(Wc, wcf, HID, LAT);   // 2

  // ---- fork: side stream does Q projection + RoPE Q ----
  cudaEventRecord(g_ctx.e0, 0);
  cudaStreamWaitEvent(g_ctx.side, g_ctx.e0, 0);
  mma_gemm_f16<<<dim3((NH * HDIM) / BN, M / BM), 256, GSMEM_F16, g_ctx.side>>>(
      xf, wqf, Qp, nullptr, M, NH * HDIM, HID, 0);  // 3 <- profiled slot
  const int totQ = B * L * NH * 64;
  rope_f16_kernel<<<(totQ + 255) / 256, 256, 0, g_ctx.side>>>(Qp, qf, NH, totQ);  // 4
  cudaEventRecord(g_ctx.e1, g_ctx.side);

  // ---- main stream: C -> K/V chain ----
  tsplit_f16_kernel<<<dim3((NKV * HDIM) / 32, LAT / 32), 256>>>(
      Wk, wkvf, LAT, NKV * HDIM);  // rows 0..511
  tsplit_f16_kernel<<<dim3((NKV * HDIM) / 32, LAT / 32), 256>>>(
      Wv, wkvf + (size_t)NKV * HDIM * LAT, LAT, NKV * HDIM);  // rows 512..1023
  mma_gemm_f16<<<dim3(LAT / BN, M / BM), 256, GSMEM_F16>>>(
      xf, wcf, nullptr, cf, M, LAT, HID, 1);
  mma_gemm_f16<<<dim3((2 * NKV * HDIM) / BN, M / BM), 256, GSMEM_F16>>>(
      cf, wkvf, Kp, vf, M, 2 * NKV * HDIM, LAT, 2);
  const int totK = B * L * NKV * 64;
  rope_f16_kernel<<<(totK + 255) / 256, 256>>>(Kp, kf, NKV, totK);
  tsplit_f16_kernel<<<dim3(HID / 32, (NH * HDIM) / 32), 256>>>(
      Wo, wof, NH * HDIM, HID);

  // ---- join, attention, output projection ----
  cudaStreamWaitEvent(0, g_ctx.e1, 0);
  attn_mma<<<dim3(L / AQ, NH, B), 256, ASMEM>>>(qf, kf, vf, mask, yf);
  mma_gemm_f16<<<dim3(HID / BN, M / BM), 256, GSMEM_F16>>>(
      yf, wof, out, nullptr, M, HID, HID, 0);
}

// round 8
// speedup vs baseline: 4.7168x; 1.0091x over previous
#include <cuda_runtime.h>
#include <cuda_fp16.h>
#include <cstdint>
#include <math.h>

#define B 2
#define L 2048
#define HID 2048
#define NH 16
#define NKV 4
#define HDIM 128
#define LAT 512
#define SCALE 0.08838834764831845f /* 1/sqrt(128) */

// ======================= helpers =======================
__device__ __forceinline__ uint32_t smem_to_u32(const void* p) {
  uint32_t a;
  asm("{ .reg .u64 t; cvta.to.shared.u64 t, %1; cvt.u32.u64 %0, t; }"
      : "=r"(a) : "l"(p));
  return a;
}
__device__ __forceinline__ void cp16(uint32_t dst, const void* src) {
  asm volatile("cp.async.cg.shared.global [%0], [%1], 16;" ::"r"(dst), "l"(src));
}
#define CP_COMMIT() asm volatile("cp.async.commit_group;" ::: "memory")
#define CP_WAIT1() asm volatile("cp.async.wait_group 1;" ::: "memory")
#define CP_WAIT0() asm volatile("cp.async.wait_group 0;" ::: "memory")

__device__ __forceinline__ void ldsm4(uint32_t addr, uint32_t* r) {
  asm volatile("ldmatrix.sync.aligned.m8n8.x4.shared.b16 {%0,%1,%2,%3}, [%4];"
               : "=r"(r[0]), "=r"(r[1]), "=r"(r[2]), "=r"(r[3]) : "r"(addr));
}
__device__ __forceinline__ void ldsm4t(uint32_t addr, uint32_t* r) {
  asm volatile(
      "ldmatrix.sync.aligned.m8n8.x4.trans.shared.b16 {%0,%1,%2,%3}, [%4];"
      : "=r"(r[0]), "=r"(r[1]), "=r"(r[2]), "=r"(r[3]) : "r"(addr));
}
__device__ __forceinline__ void mma16816h(float* c, const uint32_t* a,
                                          const uint32_t* b) {
  asm volatile(
      "mma.sync.aligned.m16n8k16.row.col.f32.f16.f16.f32 "
      "{%0,%1,%2,%3}, {%4,%5,%6,%7}, {%8,%9}, {%0,%1,%2,%3};"
      : "+f"(c[0]), "+f"(c[1]), "+f"(c[2]), "+f"(c[3])
      : "r"(a[0]), "r"(a[1]), "r"(a[2]), "r"(a[3]), "r"(b[0]), "r"(b[1]));
}
__device__ __forceinline__ uint32_t pk2h(float lo, float hi) {
  __half2 h = __floats2half2_rn(lo, hi);
  return *(uint32_t*)&h;
}

// ======================= scratch =======================
__device__ float g_Q[(size_t)B * L * NH * HDIM];
__device__ float g_K[(size_t)B * L * NKV * HDIM];

__device__ __half g_xf[(size_t)B * L * HID];
__device__ __half g_cf[(size_t)B * L * LAT];
__device__ __half g_Qf[(size_t)B * L * NH * HDIM];
__device__ __half g_Kf[(size_t)B * L * NKV * HDIM];
__device__ __half g_Vf[(size_t)B * L * NKV * HDIM];
__device__ __half g_Yf[(size_t)B * L * HID];
__device__ __half g_Wqt_f[(size_t)NH * HDIM * HID];
__device__ __half g_Wct_f[(size_t)LAT * HID];
__device__ __half g_Wkvt_f[(size_t)2 * NKV * HDIM * LAT];  // [Wk; Wv] rows
__device__ __half g_Wot_f[(size_t)HID * NH * HDIM];

// ======================= stream context (created pre-main) ==============
namespace {
struct Ctx {
  cudaStream_t side;
  cudaEvent_t e0, e1;
  Ctx() {
    cudaStreamCreateWithFlags(&side, cudaStreamNonBlocking);
    cudaEventCreateWithFlags(&e0, cudaEventDisableTiming);
    cudaEventCreateWithFlags(&e1, cudaEventDisableTiming);
  }
};
Ctx g_ctx;
}  // namespace

// ======================= preprocessing =======================
__global__ void split_f16_kernel(const float* __restrict__ s,
                                 __half* __restrict__ f, int n4) {
  int i = blockIdx.x * blockDim.x + threadIdx.x;
  if (i >= n4) return;
  float4 v = ((const float4*)s)[i];
  ((__half2*)f)[2 * i] = __floats2half2_rn(v.x, v.y);
  ((__half2*)f)[2 * i + 1] = __floats2half2_rn(v.z, v.w);
}

// W[K,N] fp32 -> Wt[N,K] fp16
__global__ __launch_bounds__(256) void tsplit_f16_kernel(
    const float* __restrict__ W, __half* __restrict__ f, int K, int N) {
  __shared__ float t[32][33];
  const int n0 = blockIdx.x * 32, k0 = blockIdx.y * 32;
  const int tx = threadIdx.x & 31, ty = threadIdx.x >> 5;
#pragma unroll
  for (int i = 0; i < 32; i += 8)
    t[ty + i][tx] = W[(size_t)(k0 + ty + i) * N + n0 + tx];
  __syncthreads();
#pragma unroll
  for (int i = 0; i < 32; i += 8)
    f[(size_t)(n0 + ty + i) * K + k0 + tx] = __float2half(t[tx][ty + i]);
}

// RoPE fp32 -> fp16, layout [B, L, H, 128]
__global__ void rope_f16_kernel(const float* __restrict__ t,
                                __half* __restrict__ f, int H, int total) {
  int i = blockIdx.x * blockDim.x + threadIdx.x;
  if (i >= total) return;
  const int hf = i & 63;
  const int h = (i >> 6) % H;
  const int bl = i / (64 * H);
  const int l = bl & (L - 1);
  const double inv = exp(-(double)hf * 0.14391156831212788);
  const double fr = (double)l * inv;
  const float c = (float)cos(fr);
  const float s = (float)sin(fr);
  const size_t base = ((size_t)bl * H + h) * HDIM;
  const float a = t[base + hf];
  const float b2 = t[base + hf + 64];
  f[base + hf] = __float2half(a * c - b2 * s);
  f[base + hf + 64] = __float2half(b2 * c + a * s);
}

// ======================= single-pass fp16 GEMM (3-stage pipeline) =========
// C[M,N] = A[M,K] @ B[N,K]^T, fp16 in, fp32 accum. BK=64, XOR-swizzled rows.
// mode 0: fp32 out; mode 1: fp16 out; mode 2: KV split.
#define BM 128
#define BN 128
#define FBK 64
#define FTILEB 16384u
#define FSTAGEB 32768u
#define GSMEM_F16 (3 * 32768)

__global__ __launch_bounds__(256) void mma_gemm_f16(
    const __half* __restrict__ A, const __half* __restrict__ Bm,
    float* __restrict__ C, __half* __restrict__ C16, int M, int N, int K,
    int mode) {
  extern __shared__ char smem[];
  const uint32_t sb = smem_to_u32(smem);
  const int tid = threadIdx.x, wid = tid >> 5, lane = tid & 31;
  const int wm = wid >> 2, wn = wid & 3;
  const int m0 = blockIdx.y * BM, n0 = blockIdx.x * BN;
  const __half* pA = A + (size_t)m0 * K;
  const __half* pB = Bm + (size_t)n0 * K;

  float acc[4][4][4];
#pragma unroll
  for (int f = 0; f < 4; f++)
#pragma unroll
    for (int n = 0; n < 4; n++)
#pragma unroll
      for (int e = 0; e < 4; e++) acc[f][n][e] = 0.f;

  auto load_stage = [&](int k0, int buf) {
    const uint32_t base = sb + buf * FSTAGEB;
#pragma unroll
    for (int i = 0; i < 4; i++) {
      const int idx = i * 256 + tid;
      const int r = idx >> 3, c = idx & 7;
      const uint32_t d = base + r * 128u + ((uint32_t)(c ^ (r & 7)) << 4);
      const size_t go = (size_t)r * K + k0 + c * 8;
      cp16(d, pA + go);
      cp16(d + FTILEB, pB + go);
    }
    CP_COMMIT();
  };

  const int S = K / FBK;
  load_stage(0, 0);
  load_stage(FBK, 1);

  const int rowa = wm * 64 + (lane & 15);
  const int rowb = wn * 32 + (lane & 7) + ((lane >> 4) << 3);

  for (int s = 0; s < S; s++) {
    const int buf = s % 3;
    if (s == S - 1) CP_WAIT0(); else CP_WAIT1();
    __syncthreads();
    if (s + 2 < S) load_stage((s + 2) * FBK, (s + 2) % 3);
    const uint32_t abase = sb + buf * FSTAGEB;
    const uint32_t bbase = abase + FTILEB;
#pragma unroll
    for (int ks = 0; ks < 4; ks++) {
      uint32_t ah[4][4], bh[2][4];
      const int ca = 2 * ks + (lane >> 4);
      const int cb = 2 * ks + ((lane >> 3) & 1);
#pragma unroll
      for (int f = 0; f < 4; f++) {
        const int rr = rowa + f * 16;
        ldsm4(abase + rr * 128u + ((uint32_t)(ca ^ (rr & 7)) << 4), ah[f]);
      }
#pragma unroll
      for (int p = 0; p < 2; p++) {
        const int rr = rowb + p * 16;
        ldsm4(bbase + rr * 128u + ((uint32_t)(cb ^ (rr & 7)) << 4), bh[p]);
      }
#pragma unroll
      for (int f = 0; f < 4; f++)
#pragma unroll
        for (int n = 0; n < 4; n++)
          mma16816h(acc[f][n], ah[f], &bh[n >> 1][(n & 1) * 2]);
    }
  }

#pragma unroll
  for (int f = 0; f < 4; f++) {
    const int row = m0 + wm * 64 + f * 16 + (lane >> 2);
#pragma unroll
    for (int n = 0; n < 4; n++) {
      const int col = n0 + wn * 32 + n * 8 + (lane & 3) * 2;
      if (mode == 0) {
        *(float2*)&C[(size_t)row * N + col] =
            make_float2(acc[f][n][0], acc[f][n][1]);
        *(float2*)&C[(size_t)(row + 8) * N + col] =
            make_float2(acc[f][n][2], acc[f][n][3]);
      } else if (mode == 1) {
        *(__half2*)&C16[(size_t)row * N + col] =
            __floats2half2_rn(acc[f][n][0], acc[f][n][1]);
        *(__half2*)&C16[(size_t)(row + 8) * N + col] =
            __floats2half2_rn(acc[f][n][2], acc[f][n][3]);
      } else {
        if (col < 512) {  // K -> fp32 (RoPE input), row stride 512
          *(float2*)&C[(size_t)row * 512 + col] =
              make_float2(acc[f][n][0], acc[f][n][1]);
          *(float2*)&C[(size_t)(row + 8) * 512 + col] =
              make_float2(acc[f][n][2], acc[f][n][3]);
        } else {  // V -> fp16, row stride 512
          const int cv = col - 512;
          *(__half2*)&C16[(size_t)row * 512 + cv] =
              __floats2half2_rn(acc[f][n][0], acc[f][n][1]);
          *(__half2*)&C16[(size_t)(row + 8) * 512 + cv] =
              __floats2half2_rn(acc[f][n][2], acc[f][n][3]);
        }
      }
    }
  }
}

// ======================= fp16 flash attention =======================
// Balanced pairing: each CTA does q-tiles (NQT-1-pair) then (pair) -> every
// CTA processes exactly 68 key tiles. 3-stage KV pipeline, 1 barrier/tile.
#define AQ 128
#define NQT (L / AQ)
#define AKT 32
#define ASMEM (3 * 16384)

__global__ __launch_bounds__(256) void attn_mma(
    const __half* __restrict__ Qf, const __half* __restrict__ Kf,
    const __half* __restrict__ Vf, const int* __restrict__ mask,
    __half* __restrict__ Yf) {
  extern __shared__ char smem[];
  const uint32_t sb = smem_to_u32(smem);
  const int pair = blockIdx.x;
  const int h = blockIdx.y, b = blockIdx.z;
  const int hkv = h >> 2;
  const int tid = threadIdx.x, w = tid >> 5, lane = tid & 31;

  const __half* khg = Kf + ((size_t)(b * L) * NKV + hkv) * 128;
  const __half* vhg = Vf + ((size_t)(b * L) * NKV + hkv) * 128;
  const int* mrow = mask + b * L;

  const int rbB = (lane & 7) + ((lane >> 4) << 3);
  const int rvB = (lane & 7) + (((lane >> 3) & 1) << 3);

  for (int half = 0; half < 2; half++) {
    const int qt = half == 0 ? (NQT - 1 - pair) : pair;  // heavy first
    const int q0 = qt * AQ;
    __syncthreads();  // prior half fully done with smem

    // ---- stage Q through smem, extract register fragments ----
    {
      const __half* qg = Qf + ((size_t)(b * L + q0) * NH + h) * 128;
#pragma unroll
      for (int i = 0; i < 8; i++) {
        const int idx = i * 256 + tid;
        const int r = idx >> 4, c = idx & 15;
        const uint32_t d = sb + r * 256u + ((uint32_t)(c ^ (r & 7)) << 4);
        cp16(d, qg + (size_t)r * (NH * 128) + c * 8);
      }
      CP_COMMIT();
      CP_WAIT0();
      __syncthreads();
    }
    uint32_t qh[8][4];
    {
      const int rowa = w * 16 + (lane & 15);
#pragma unroll
      for (int kd = 0; kd < 8; kd++) {
        const int ca = 2 * kd + (lane >> 4);
        ldsm4(sb + rowa * 256u + ((uint32_t)(ca ^ (rowa & 7)) << 4), qh[kd]);
      }
    }
    __syncthreads();  // Q smem free for KV buffers

    float o[16][4];
#pragma unroll
    for (int nf = 0; nf < 16; nf++)
#pragma unroll
      for (int e = 0; e < 4; e++) o[nf][e] = 0.f;
    float m2[2] = {-1e30f, -1e30f}, ls[2] = {0.f, 0.f};

    auto load_kv = [&](int t, int buf) {
      const int k0 = t * AKT;
      const uint32_t base = sb + buf * 16384u;
#pragma unroll
      for (int i = 0; i < 2; i++) {
        const int idx = i * 256 + tid;
        const int r = idx >> 4, c = idx & 15;
        const uint32_t d = base + r * 256u + ((uint32_t)(c ^ (r & 7)) << 4);
        const size_t go = (size_t)(k0 + r) * (NKV * 128) + c * 8;
        cp16(d, khg + go);
        cp16(d + 8192u, vhg + go);
      }
      CP_COMMIT();
    };

    const int nkt = qt * 4 + 4;
    load_kv(0, 0);
    if (nkt > 1) load_kv(1, 1);

    const int qa = q0 + w * 16 + (lane >> 2);
    const int qb = qa + 8;

    for (int kt = 0; kt < nkt; kt++) {
      const int buf = kt % 3;
      const int k0 = kt * AKT;
      if (kt >= nkt - 1) CP_WAIT0(); else CP_WAIT1();
      __syncthreads();
      if (kt + 2 < nkt) load_kv(kt + 2, (kt + 2) % 3);

      if (k0 <= q0 + w * 16 + 15) {
        const uint32_t kb = sb + buf * 16384u;
        float s[4][4];
#pragma unroll
        for (int n = 0; n < 4; n++)
#pragma unroll
          for (int e = 0; e < 4; e++) s[n][e] = 0.f;

#pragma unroll
        for (int kd = 0; kd < 8; kd++) {
          const int cb = 2 * kd + ((lane >> 3) & 1);
          const uint32_t b0a =
              kb + (uint32_t)rbB * 256u + ((uint32_t)(cb ^ (rbB & 7)) << 4);
          uint32_t bh0[4], bh1[4];
          ldsm4(b0a, bh0);
          ldsm4(b0a + 16u * 256u, bh1);
#pragma unroll
          for (int n = 0; n < 4; n++) {
            const uint32_t* bp =
                (n < 2) ? &bh0[(n & 1) * 2] : &bh1[(n & 1) * 2];
            mma16816h(s[n], qh[kd], bp);
          }
        }

        float rmax[2] = {-1e30f, -1e30f};
#pragma unroll
        for (int n = 0; n < 4; n++) {
          const int col = k0 + n * 8 + (lane & 3) * 2;
          const bool mk0 = mrow[col] > 0, mk1 = mrow[col + 1] > 0;
          s[n][0] = (mk0 && col <= qa) ? s[n][0] * SCALE : -1e30f;
          s[n][1] = (mk1 && col + 1 <= qa) ? s[n][1] * SCALE : -1e30f;
          s[n][2] = (mk0 && col <= qb) ? s[n][2] * SCALE : -1e30f;
          s[n][3] = (mk1 && col + 1 <= qb) ? s[n][3] * SCALE : -1e30f;
          rmax[0] = fmaxf(rmax[0], fmaxf(s[n][0], s[n][1]));
          rmax[1] = fmaxf(rmax[1], fmaxf(s[n][2], s[n][3]));
        }
#pragma unroll
        for (int off = 1; off <= 2; off <<= 1) {
          rmax[0] = fmaxf(rmax[0], __shfl_xor_sync(0xffffffffu, rmax[0], off));
          rmax[1] = fmaxf(rmax[1], __shfl_xor_sync(0xffffffffu, rmax[1], off));
        }
        const float mn0 = fmaxf(m2[0], rmax[0]);
        const float mn1 = fmaxf(m2[1], rmax[1]);
        const float al0 = __expf(m2[0] - mn0);
        const float al1 = __expf(m2[1] - mn1);
        m2[0] = mn0;
        m2[1] = mn1;
        float ps0 = 0.f, ps1 = 0.f;
#pragma unroll
        for (int n = 0; n < 4; n++) {
          s[n][0] = __expf(s[n][0] - mn0);
          s[n][1] = __expf(s[n][1] - mn0);
          s[n][2] = __expf(s[n][2] - mn1);
          s[n][3] = __expf(s[n][3] - mn1);
          ps0 += s[n][0] + s[n][1];
          ps1 += s[n][2] + s[n][3];
        }
#pragma unroll
        for (int off = 1; off <= 2; off <<= 1) {
          ps0 += __shfl_xor_sync(0xffffffffu, ps0, off);
          ps1 += __shfl_xor_sync(0xffffffffu, ps1, off);
        }
        ls[0] = ls[0] * al0 + ps0;
        ls[1] = ls[1] * al1 + ps1;
#pragma unroll
        for (int nf = 0; nf < 16; nf++) {
          o[nf][0] *= al0;
          o[nf][1] *= al0;
          o[nf][2] *= al1;
          o[nf][3] *= al1;
        }

        uint32_t pa[2][4];
#pragma unroll
        for (int ks = 0; ks < 2; ks++) {
          pa[ks][0] = pk2h(s[2 * ks][0], s[2 * ks][1]);
          pa[ks][1] = pk2h(s[2 * ks][2], s[2 * ks][3]);
          pa[ks][2] = pk2h(s[2 * ks + 1][0], s[2 * ks + 1][1]);
          pa[ks][3] = pk2h(s[2 * ks + 1][2], s[2 * ks + 1][3]);
        }

        const uint32_t vb = kb + 8192u;
#pragma unroll
        for (int ks = 0; ks < 2; ks++) {
          const int rowv = 16 * ks + rvB;
#pragma unroll
          for (int j = 0; j < 8; j++) {
            const int cv = 2 * j + (lane >> 4);
            uint32_t vhf[4];
            ldsm4t(vb + (uint32_t)rowv * 256u +
                       ((uint32_t)(cv ^ (rowv & 7)) << 4),
                   vhf);
            mma16816h(o[2 * j], pa[ks], &vhf[0]);
            mma16816h(o[2 * j + 1], pa[ks], &vhf[2]);
          }
        }
      }
    }

    const float inv0 = 1.f / ls[0], inv1 = 1.f / ls[1];
    const size_t rA = (size_t)(b * L + qa) * (size_t)HID + h * 128;
    const size_t rB = rA + (size_t)8 * HID;
#pragma unroll
    for (int nf = 0; nf < 16; nf++) {
      const int d = nf * 8 + (lane & 3) * 2;
      *(__half2*)&Yf[rA + d] =
          __floats2half2_rn(o[nf][0] * inv0, o[nf][1] * inv0);
      *(__half2*)&Yf[rB + d] =
          __floats2half2_rn(o[nf][2] * inv1, o[nf][3] * inv1);
    }
  }
}

// ======================= launch =======================
extern "C" void kernel_launch(void* const* d_in, const int* in_sizes, int n_in,
                              void* d_out, int out_size) {
  const float* x = (const float*)d_in[0];
  const float* Wq = (const float*)d_in[1];
  const float* Wc = (const float*)d_in[2];
  const float* Wk = (const float*)d_in[3];
  const float* Wv = (const float*)d_in[4];
  const float* Wo = (const float*)d_in[5];
  const int* mask = (const int*)d_in[6];
  float* out = (float*)d_out;

  float *Qp, *Kp;
  cudaGetSymbolAddress((void**)&Qp, g_Q);
  cudaGetSymbolAddress((void**)&Kp, g_K);
  __half *xf, *cf, *qf, *kf, *vf, *yf, *wqf, *wcf, *wkvf, *wof;
  cudaGetSymbolAddress((void**)&xf, g_xf);
  cudaGetSymbolAddress((void**)&cf, g_cf);
  cudaGetSymbolAddress((void**)&qf, g_Qf);
  cudaGetSymbolAddress((void**)&kf, g_Kf);
  cudaGetSymbolAddress((void**)&vf, g_Vf);
  cudaGetSymbolAddress((void**)&yf, g_Yf);
  cudaGetSymbolAddress((void**)&wqf, g_Wqt_f);
  cudaGetSymbolAddress((void**)&wcf, g_Wct_f);
  cudaGetSymbolAddress((void**)&wkvf, g_Wkvt_f);
  cudaGetSymbolAddress((void**)&wof, g_Wot_f);

  const int M = B * L;  // 4096

  cudaFuncSetAttribute(mma_gemm_f16, cudaFuncAttributeMaxDynamicSharedMemorySize,
                       GSMEM_F16);
  cudaFuncSetAttribute(attn_mma, cudaFuncAttributeMaxDynamicSharedMemorySize,
                       ASMEM);

  // ---- main stream: shared preprocessing ----
  split_f16_kernel<<<(M * HID / 4 + 255) / 256, 256>>>(x, xf, M * HID / 4);
  tsplit_f16_kernel<<<dim3((NH * HDIM) / 32, HID / 32), 256>>>(
      Wq, wqf, HID, NH * HDIM);
  tsplit_f16_kernel<<<dim3(LAT / 32, HID / 32), 256>>>(Wc, wcf, HID, LAT);

  // ---- fork: side stream does Q projection + RoPE Q ----
  cudaEventRecord(g_ctx.e0, 0);
  cudaStreamWaitEvent(g_ctx.side, g_ctx.e0, 0);
  mma_gemm_f16<<<dim3((NH * HDIM) / BN, M / BM), 256, GSMEM_F16, g_ctx.side>>>(
      xf, wqf, Qp, nullptr, M, NH * HDIM, HID, 0);  // <- profiled slot
  const int totQ = B * L * NH * 64;
  rope_f16_kernel<<<(totQ + 255) / 256, 256, 0, g_ctx.side>>>(Qp, qf, NH, totQ);
  cudaEventRecord(g_ctx.e1, g_ctx.side);

  // ---- main stream: C -> K/V chain ----
  tsplit_f16_kernel<<<dim3((NKV * HDIM) / 32, LAT / 32), 256>>>(
      Wk, wkvf, LAT, NKV * HDIM);  // rows 0..511
  tsplit_f16_kernel<<<dim3((NKV * HDIM) / 32, LAT / 32), 256>>>(
      Wv, wkvf + (size_t)NKV * HDIM * LAT, LAT, NKV * HDIM);  // rows 512..1023
  mma_gemm_f16<<<dim3(LAT / BN, M / BM), 256, GSMEM_F16>>>(
      xf, wcf, nullptr, cf, M, LAT, HID, 1);
  mma_gemm_f16<<<dim3((2 * NKV * HDIM) / BN, M / BM), 256, GSMEM_F16>>>(
      cf, wkvf, Kp, vf, M, 2 * NKV * HDIM, LAT, 2);
  const int totK = B * L * NKV * 64;
  rope_f16_kernel<<<(totK + 255) / 256, 256>>>(Kp, kf, NKV, totK);
  tsplit_f16_kernel<<<dim3(HID / 32, (NH * HDIM) / 32), 256>>>(
      Wo, wof, NH * HDIM, HID);

  // ---- join, attention, output projection ----
  cudaStreamWaitEvent(0, g_ctx.e1, 0);
  attn_mma<<<dim3(NQT / 2, NH, B), 256, ASMEM>>>(qf, kf, vf, mask, yf);
  mma_gemm_f16<<<dim3(HID / BN, M / BM), 256, GSMEM_F16>>>(
      yf, wof, out, nullptr, M, HID, HID, 0);
}

// round 9
// speedup vs baseline: 10.8784x; 2.3063x over previous
#include <cuda_runtime.h>
#include <cuda_fp16.h>
#include <cstdint>
#include <math.h>

#define B 2
#define L 2048
#define HID 2048
#define NH 16
#define NKV 4
#define HDIM 128
#define LAT 512
#define SCALE 0.08838834764831845f /* 1/sqrt(128) */

// ======================= helpers =======================
__device__ __forceinline__ uint32_t smem_to_u32(const void* p) {
  uint32_t a;
  asm("{ .reg .u64 t; cvta.to.shared.u64 t, %1; cvt.u32.u64 %0, t; }"
      : "=r"(a) : "l"(p));
  return a;
}
__device__ __forceinline__ void cp16(uint32_t dst, const void* src) {
  asm volatile("cp.async.cg.shared.global [%0], [%1], 16;" ::"r"(dst), "l"(src));
}
#define CP_COMMIT() asm volatile("cp.async.commit_group;" ::: "memory")
#define CP_WAIT1() asm volatile("cp.async.wait_group 1;" ::: "memory")
#define CP_WAIT0() asm volatile("cp.async.wait_group 0;" ::: "memory")

__device__ __forceinline__ void ldsm4(uint32_t addr, uint32_t* r) {
  asm volatile("ldmatrix.sync.aligned.m8n8.x4.shared.b16 {%0,%1,%2,%3}, [%4];"
               : "=r"(r[0]), "=r"(r[1]), "=r"(r[2]), "=r"(r[3]) : "r"(addr));
}
__device__ __forceinline__ void ldsm4t(uint32_t addr, uint32_t* r) {
  asm volatile(
      "ldmatrix.sync.aligned.m8n8.x4.trans.shared.b16 {%0,%1,%2,%3}, [%4];"
      : "=r"(r[0]), "=r"(r[1]), "=r"(r[2]), "=r"(r[3]) : "r"(addr));
}
__device__ __forceinline__ void mma16816h(float* c, const uint32_t* a,
                                          const uint32_t* b) {
  asm volatile(
      "mma.sync.aligned.m16n8k16.row.col.f32.f16.f16.f32 "
      "{%0,%1,%2,%3}, {%4,%5,%6,%7}, {%8,%9}, {%0,%1,%2,%3};"
      : "+f"(c[0]), "+f"(c[1]), "+f"(c[2]), "+f"(c[3])
      : "r"(a[0]), "r"(a[1]), "r"(a[2]), "r"(a[3]), "r"(b[0]), "r"(b[1]));
}
__device__ __forceinline__ uint32_t pk2h(float lo, float hi) {
  __half2 h = __floats2half2_rn(lo, hi);
  return *(uint32_t*)&h;
}

// ======================= scratch =======================
__device__ float g_Q[(size_t)B * L * NH * HDIM];
__device__ float g_K[(size_t)B * L * NKV * HDIM];
__device__ float2 g_tab[(size_t)L * 64];  // RoPE cos/sin table

__device__ __half g_xf[(size_t)B * L * HID];
__device__ __half g_cf[(size_t)B * L * LAT];
__device__ __half g_Qf[(size_t)B * L * NH * HDIM];
__device__ __half g_Kf[(size_t)B * L * NKV * HDIM];
__device__ __half g_Vf[(size_t)B * L * NKV * HDIM];
__device__ __half g_Yf[(size_t)B * L * HID];
__device__ __half g_Wqt_f[(size_t)NH * HDIM * HID];
__device__ __half g_Wct_f[(size_t)LAT * HID];
__device__ __half g_Wkvt_f[(size_t)2 * NKV * HDIM * LAT];  // [Wk; Wv] rows
__device__ __half g_Wot_f[(size_t)HID * NH * HDIM];

// ======================= stream context (created pre-main) ==============
namespace {
struct Ctx {
  cudaStream_t side;
  cudaEvent_t e0, e1, e2;
  Ctx() {
    cudaStreamCreateWithFlags(&side, cudaStreamNonBlocking);
    cudaEventCreateWithFlags(&e0, cudaEventDisableTiming);
    cudaEventCreateWithFlags(&e1, cudaEventDisableTiming);
    cudaEventCreateWithFlags(&e2, cudaEventDisableTiming);
  }
};
Ctx g_ctx;
}  // namespace

// ======================= preprocessing =======================
__global__ void split_f16_kernel(const float* __restrict__ s,
                                 __half* __restrict__ f, int n4) {
  int i = blockIdx.x * blockDim.x + threadIdx.x;
  if (i >= n4) return;
  float4 v = ((const float4*)s)[i];
  ((__half2*)f)[2 * i] = __floats2half2_rn(v.x, v.y);
  ((__half2*)f)[2 * i + 1] = __floats2half2_rn(v.z, v.w);
}

// W[K,N] fp32 -> Wt[N,K] fp16
__global__ __launch_bounds__(256) void tsplit_f16_kernel(
    const float* __restrict__ W, __half* __restrict__ f, int K, int N) {
  __shared__ float t[32][33];
  const int n0 = blockIdx.x * 32, k0 = blockIdx.y * 32;
  const int tx = threadIdx.x & 31, ty = threadIdx.x >> 5;
#pragma unroll
  for (int i = 0; i < 32; i += 8)
    t[ty + i][tx] = W[(size_t)(k0 + ty + i) * N + n0 + tx];
  __syncthreads();
#pragma unroll
  for (int i = 0; i < 32; i += 8)
    f[(size_t)(n0 + ty + i) * K + k0 + tx] = __float2half(t[tx][ty + i]);
}

// RoPE table: tab[l][hf] = (cos, sin)(l * 10000^(-hf/64)), double precision
__global__ void rope_tab_kernel(float2* __restrict__ tab) {
  int i = blockIdx.x * blockDim.x + threadIdx.x;
  if (i >= L * 64) return;
  const int hf = i & 63;
  const int l = i >> 6;
  const double inv = exp(-(double)hf * 0.14391156831212788);
  const double fr = (double)l * inv;
  tab[i] = make_float2((float)cos(fr), (float)sin(fr));
}

// RoPE fp32 -> fp16 via table, layout [B, L, H, 128]
__global__ void rope_f16_kernel(const float* __restrict__ t,
                                const float2* __restrict__ tab,
                                __half* __restrict__ f, int H, int total) {
  int i = blockIdx.x * blockDim.x + threadIdx.x;
  if (i >= total) return;
  const int hf = i & 63;
  const int h = (i >> 6) % H;
  const int bl = i / (64 * H);
  const int l = bl & (L - 1);
  const float2 cs = tab[l * 64 + hf];
  const size_t base = ((size_t)bl * H + h) * HDIM;
  const float a = t[base + hf];
  const float b2 = t[base + hf + 64];
  f[base + hf] = __float2half(a * cs.x - b2 * cs.y);
  f[base + hf + 64] = __float2half(b2 * cs.x + a * cs.y);
}

// ======================= single-pass fp16 GEMM (3-stage pipeline) =========
// C[M,N] = A[M,K] @ B[N,K]^T, fp16 in, fp32 accum. BK=64, XOR-swizzled rows.
// mode 0: fp32 out; mode 1: fp16 out; mode 2: KV split.
#define BM 128
#define BN 128
#define FBK 64
#define FTILEB 16384u
#define FSTAGEB 32768u
#define GSMEM_F16 (3 * 32768)

__global__ __launch_bounds__(256) void mma_gemm_f16(
    const __half* __restrict__ A, const __half* __restrict__ Bm,
    float* __restrict__ C, __half* __restrict__ C16, int M, int N, int K,
    int mode) {
  extern __shared__ char smem[];
  const uint32_t sb = smem_to_u32(smem);
  const int tid = threadIdx.x, wid = tid >> 5, lane = tid & 31;
  const int wm = wid >> 2, wn = wid & 3;
  const int m0 = blockIdx.y * BM, n0 = blockIdx.x * BN;
  const __half* pA = A + (size_t)m0 * K;
  const __half* pB = Bm + (size_t)n0 * K;

  float acc[4][4][4];
#pragma unroll
  for (int f = 0; f < 4; f++)
#pragma unroll
    for (int n = 0; n < 4; n++)
#pragma unroll
      for (int e = 0; e < 4; e++) acc[f][n][e] = 0.f;

  auto load_stage = [&](int k0, int buf) {
    const uint32_t base = sb + buf * FSTAGEB;
#pragma unroll
    for (int i = 0; i < 4; i++) {
      const int idx = i * 256 + tid;
      const int r = idx >> 3, c = idx & 7;
      const uint32_t d = base + r * 128u + ((uint32_t)(c ^ (r & 7)) << 4);
      const size_t go = (size_t)r * K + k0 + c * 8;
      cp16(d, pA + go);
      cp16(d + FTILEB, pB + go);
    }
    CP_COMMIT();
  };

  const int S = K / FBK;
  load_stage(0, 0);
  load_stage(FBK, 1);

  const int rowa = wm * 64 + (lane & 15);
  const int rowb = wn * 32 + (lane & 7) + ((lane >> 4) << 3);

  for (int s = 0; s < S; s++) {
    const int buf = s % 3;
    if (s == S - 1) CP_WAIT0(); else CP_WAIT1();
    __syncthreads();
    if (s + 2 < S) load_stage((s + 2) * FBK, (s + 2) % 3);
    const uint32_t abase = sb + buf * FSTAGEB;
    const uint32_t bbase = abase + FTILEB;
#pragma unroll
    for (int ks = 0; ks < 4; ks++) {
      uint32_t ah[4][4], bh[2][4];
      const int ca = 2 * ks + (lane >> 4);
      const int cb = 2 * ks + ((lane >> 3) & 1);
#pragma unroll
      for (int f = 0; f < 4; f++) {
        const int rr = rowa + f * 16;
        ldsm4(abase + rr * 128u + ((uint32_t)(ca ^ (rr & 7)) << 4), ah[f]);
      }
#pragma unroll
      for (int p = 0; p < 2; p++) {
        const int rr = rowb + p * 16;
        ldsm4(bbase + rr * 128u + ((uint32_t)(cb ^ (rr & 7)) << 4), bh[p]);
      }
#pragma unroll
      for (int f = 0; f < 4; f++)
#pragma unroll
        for (int n = 0; n < 4; n++)
          mma16816h(acc[f][n], ah[f], &bh[n >> 1][(n & 1) * 2]);
    }
  }

#pragma unroll
  for (int f = 0; f < 4; f++) {
    const int row = m0 + wm * 64 + f * 16 + (lane >> 2);
#pragma unroll
    for (int n = 0; n < 4; n++) {
      const int col = n0 + wn * 32 + n * 8 + (lane & 3) * 2;
      if (mode == 0) {
        *(float2*)&C[(size_t)row * N + col] =
            make_float2(acc[f][n][0], acc[f][n][1]);
        *(float2*)&C[(size_t)(row + 8) * N + col] =
            make_float2(acc[f][n][2], acc[f][n][3]);
      } else if (mode == 1) {
        *(__half2*)&C16[(size_t)row * N + col] =
            __floats2half2_rn(acc[f][n][0], acc[f][n][1]);
        *(__half2*)&C16[(size_t)(row + 8) * N + col] =
            __floats2half2_rn(acc[f][n][2], acc[f][n][3]);
      } else {
        if (col < 512) {  // K -> fp32 (RoPE input), row stride 512
          *(float2*)&C[(size_t)row * 512 + col] =
              make_float2(acc[f][n][0], acc[f][n][1]);
          *(float2*)&C[(size_t)(row + 8) * 512 + col] =
              make_float2(acc[f][n][2], acc[f][n][3]);
        } else {  // V -> fp16, row stride 512
          const int cv = col - 512;
          *(__half2*)&C16[(size_t)row * 512 + cv] =
              __floats2half2_rn(acc[f][n][0], acc[f][n][1]);
          *(__half2*)&C16[(size_t)(row + 8) * 512 + cv] =
              __floats2half2_rn(acc[f][n][2], acc[f][n][3]);
        }
      }
    }
  }
}

// ======================= fp16 flash attention =======================
// Balanced pairing: each CTA does q-tiles (NQT-1-pair) then (pair).
// Q kept in smem (not registers) so regs <= 128 -> 2 CTAs/SM.
#define AQ 128
#define NQT (L / AQ)
#define AKT 32
#define ASMEM (3 * 16384 + 32768) /* 3 KV stages + Q region = 80KB */

__global__ __launch_bounds__(256, 2) void attn_mma(
    const __half* __restrict__ Qf, const __half* __restrict__ Kf,
    const __half* __restrict__ Vf, const int* __restrict__ mask,
    __half* __restrict__ Yf) {
  extern __shared__ char smem[];
  const uint32_t sb = smem_to_u32(smem);
  const uint32_t sbQ = sb + 3 * 16384u;
  const int pair = blockIdx.x;
  const int h = blockIdx.y, b = blockIdx.z;
  const int hkv = h >> 2;
  const int tid = threadIdx.x, w = tid >> 5, lane = tid & 31;

  const __half* khg = Kf + ((size_t)(b * L) * NKV + hkv) * 128;
  const __half* vhg = Vf + ((size_t)(b * L) * NKV + hkv) * 128;
  const int* mrow = mask + b * L;

  const int rbB = (lane & 7) + ((lane >> 4) << 3);
  const int rvB = (lane & 7) + (((lane >> 3) & 1) << 3);
  const int rowa = w * 16 + (lane & 15);
  const uint32_t qrow = sbQ + (uint32_t)rowa * 256u;

  for (int half = 0; half < 2; half++) {
    const int qt = half == 0 ? (NQT - 1 - pair) : pair;  // heavy first
    const int q0 = qt * AQ;
    __syncthreads();  // prior half fully done with smem

    // ---- stage Q into persistent smem region ----
    {
      const __half* qg = Qf + ((size_t)(b * L + q0) * NH + h) * 128;
#pragma unroll
      for (int i = 0; i < 8; i++) {
        const int idx = i * 256 + tid;
        const int r = idx >> 4, c = idx & 15;
        const uint32_t d = sbQ + r * 256u + ((uint32_t)(c ^ (r & 7)) << 4);
        cp16(d, qg + (size_t)r * (NH * 128) + c * 8);
      }
      CP_COMMIT();
      CP_WAIT0();
      __syncthreads();
    }

    float o[16][4];
#pragma unroll
    for (int nf = 0; nf < 16; nf++)
#pragma unroll
      for (int e = 0; e < 4; e++) o[nf][e] = 0.f;
    float m2[2] = {-1e30f, -1e30f}, ls[2] = {0.f, 0.f};

    auto load_kv = [&](int t, int buf) {
      const int k0 = t * AKT;
      const uint32_t base = sb + buf * 16384u;
#pragma unroll
      for (int i = 0; i < 2; i++) {
        const int idx = i * 256 + tid;
        const int r = idx >> 4, c = idx & 15;
        const uint32_t d = base + r * 256u + ((uint32_t)(c ^ (r & 7)) << 4);
        const size_t go = (size_t)(k0 + r) * (NKV * 128) + c * 8;
        cp16(d, khg + go);
        cp16(d + 8192u, vhg + go);
      }
      CP_COMMIT();
    };

    const int nkt = qt * 4 + 4;
    load_kv(0, 0);
    if (nkt > 1) load_kv(1, 1);

    const int qa = q0 + w * 16 + (lane >> 2);
    const int qb = qa + 8;

    for (int kt = 0; kt < nkt; kt++) {
      const int buf = kt % 3;
      const int k0 = kt * AKT;
      if (kt >= nkt - 1) CP_WAIT0(); else CP_WAIT1();
      __syncthreads();
      if (kt + 2 < nkt) load_kv(kt + 2, (kt + 2) % 3);

      if (k0 <= q0 + w * 16 + 15) {
        const uint32_t kb = sb + buf * 16384u;
        float s[4][4];
#pragma unroll
        for (int n = 0; n < 4; n++)
#pragma unroll
          for (int e = 0; e < 4; e++) s[n][e] = 0.f;

#pragma unroll
        for (int kd = 0; kd < 8; kd++) {
          const int ca = 2 * kd + (lane >> 4);
          uint32_t qf4[4];
          ldsm4(qrow + ((uint32_t)(ca ^ (rowa & 7)) << 4), qf4);
          const int cb = 2 * kd + ((lane >> 3) & 1);
          const uint32_t b0a =
              kb + (uint32_t)rbB * 256u + ((uint32_t)(cb ^ (rbB & 7)) << 4);
          uint32_t bh0[4], bh1[4];
          ldsm4(b0a, bh0);
          ldsm4(b0a + 16u * 256u, bh1);
#pragma unroll
          for (int n = 0; n < 4; n++) {
            const uint32_t* bp =
                (n < 2) ? &bh0[(n & 1) * 2] : &bh1[(n & 1) * 2];
            mma16816h(s[n], qf4, bp);
          }
        }

        float rmax[2] = {-1e30f, -1e30f};
#pragma unroll
        for (int n = 0; n < 4; n++) {
          const int col = k0 + n * 8 + (lane & 3) * 2;
          const bool mk0 = mrow[col] > 0, mk1 = mrow[col + 1] > 0;
          s[n][0] = (mk0 && col <= qa) ? s[n][0] * SCALE : -1e30f;
          s[n][1] = (mk1 && col + 1 <= qa) ? s[n][1] * SCALE : -1e30f;
          s[n][2] = (mk0 && col <= qb) ? s[n][2] * SCALE : -1e30f;
          s[n][3] = (mk1 && col + 1 <= qb) ? s[n][3] * SCALE : -1e30f;
          rmax[0] = fmaxf(rmax[0], fmaxf(s[n][0], s[n][1]));
          rmax[1] = fmaxf(rmax[1], fmaxf(s[n][2], s[n][3]));
        }
#pragma unroll
        for (int off = 1; off <= 2; off <<= 1) {
          rmax[0] = fmaxf(rmax[0], __shfl_xor_sync(0xffffffffu, rmax[0], off));
          rmax[1] = fmaxf(rmax[1], __shfl_xor_sync(0xffffffffu, rmax[1], off));
        }
        const float mn0 = fmaxf(m2[0], rmax[0]);
        const float mn1 = fmaxf(m2[1], rmax[1]);
        const bool noup =
            __all_sync(0xffffffffu, (mn0 == m2[0]) & (mn1 == m2[1]));
        if (!noup) {
          const float al0 = __expf(m2[0] - mn0);
          const float al1 = __expf(m2[1] - mn1);
          ls[0] *= al0;
          ls[1] *= al1;
#pragma unroll
          for (int nf = 0; nf < 16; nf++) {
            o[nf][0] *= al0;
            o[nf][1] *= al0;
            o[nf][2] *= al1;
            o[nf][3] *= al1;
          }
          m2[0] = mn0;
          m2[1] = mn1;
        }
        float ps0 = 0.f, ps1 = 0.f;
#pragma unroll
        for (int n = 0; n < 4; n++) {
          s[n][0] = __expf(s[n][0] - m2[0]);
          s[n][1] = __expf(s[n][1] - m2[0]);
          s[n][2] = __expf(s[n][2] - m2[1]);
          s[n][3] = __expf(s[n][3] - m2[1]);
          ps0 += s[n][0] + s[n][1];
          ps1 += s[n][2] + s[n][3];
        }
#pragma unroll
        for (int off = 1; off <= 2; off <<= 1) {
          ps0 += __shfl_xor_sync(0xffffffffu, ps0, off);
          ps1 += __shfl_xor_sync(0xffffffffu, ps1, off);
        }
        ls[0] += ps0;
        ls[1] += ps1;

        uint32_t pa[2][4];
#pragma unroll
        for (int ks = 0; ks < 2; ks++) {
          pa[ks][0] = pk2h(s[2 * ks][0], s[2 * ks][1]);
          pa[ks][1] = pk2h(s[2 * ks][2], s[2 * ks][3]);
          pa[ks][2] = pk2h(s[2 * ks + 1][0], s[2 * ks + 1][1]);
          pa[ks][3] = pk2h(s[2 * ks + 1][2], s[2 * ks + 1][3]);
        }

        const uint32_t vb = kb + 8192u;
#pragma unroll
        for (int ks = 0; ks < 2; ks++) {
          const int rowv = 16 * ks + rvB;
#pragma unroll
          for (int j = 0; j < 8; j++) {
            const int cv = 2 * j + (lane >> 4);
            uint32_t vhf[4];
            ldsm4t(vb + (uint32_t)rowv * 256u +
                       ((uint32_t)(cv ^ (rowv & 7)) << 4),
                   vhf);
            mma16816h(o[2 * j], pa[ks], &vhf[0]);
            mma16816h(o[2 * j + 1], pa[ks], &vhf[2]);
          }
        }
      }
    }

    const float inv0 = 1.f / ls[0], inv1 = 1.f / ls[1];
    const size_t rA = (size_t)(b * L + qa) * (size_t)HID + h * 128;
    const size_t rB = rA + (size_t)8 * HID;
#pragma unroll
    for (int nf = 0; nf < 16; nf++) {
      const int d = nf * 8 + (lane & 3) * 2;
      *(__half2*)&Yf[rA + d] =
          __floats2half2_rn(o[nf][0] * inv0, o[nf][1] * inv0);
      *(__half2*)&Yf[rB + d] =
          __floats2half2_rn(o[nf][2] * inv1, o[nf][3] * inv1);
    }
  }
}

// ======================= launch =======================
extern "C" void kernel_launch(void* const* d_in, const int* in_sizes, int n_in,
                              void* d_out, int out_size) {
  const float* x = (const float*)d_in[0];
  const float* Wq = (const float*)d_in[1];
  const float* Wc = (const float*)d_in[2];
  const float* Wk = (const float*)d_in[3];
  const float* Wv = (const float*)d_in[4];
  const float* Wo = (const float*)d_in[5];
  const int* mask = (const int*)d_in[6];
  float* out = (float*)d_out;

  float *Qp, *Kp;
  float2* tab;
  cudaGetSymbolAddress((void**)&Qp, g_Q);
  cudaGetSymbolAddress((void**)&Kp, g_K);
  cudaGetSymbolAddress((void**)&tab, g_tab);
  __half *xf, *cf, *qf, *kf, *vf, *yf, *wqf, *wcf, *wkvf, *wof;
  cudaGetSymbolAddress((void**)&xf, g_xf);
  cudaGetSymbolAddress((void**)&cf, g_cf);
  cudaGetSymbolAddress((void**)&qf, g_Qf);
  cudaGetSymbolAddress((void**)&kf, g_Kf);
  cudaGetSymbolAddress((void**)&vf, g_Vf);
  cudaGetSymbolAddress((void**)&yf, g_Yf);
  cudaGetSymbolAddress((void**)&wqf, g_Wqt_f);
  cudaGetSymbolAddress((void**)&wcf, g_Wct_f);
  cudaGetSymbolAddress((void**)&wkvf, g_Wkvt_f);
  cudaGetSymbolAddress((void**)&wof, g_Wot_f);

  const int M = B * L;  // 4096

  cudaFuncSetAttribute(mma_gemm_f16, cudaFuncAttributeMaxDynamicSharedMemorySize,
                       GSMEM_F16);
  cudaFuncSetAttribute(attn_mma, cudaFuncAttributeMaxDynamicSharedMemorySize,
                       ASMEM);

  // ---- main stream: shared preprocessing ----
  split_f16_kernel<<<(M * HID / 4 + 255) / 256, 256>>>(x, xf, M * HID / 4);  // 0
  tsplit_f16_kernel<<<dim3((NH * HDIM) / 32, HID / 32), 256>>>(
      Wq, wqf, HID, NH * HDIM);                                              // 1
  tsplit_f16_kernel<<<dim3(LAT / 32, HID / 32), 256>>>(Wc, wcf, HID, LAT);   // 2

  // ---- fork: side stream does Q projection ----
  cudaEventRecord(g_ctx.e0, 0);
  cudaStreamWaitEvent(g_ctx.side, g_ctx.e0, 0);
  mma_gemm_f16<<<dim3((NH * HDIM) / BN, M / BM), 256, GSMEM_F16, g_ctx.side>>>(
      xf, wqf, Qp, nullptr, M, NH * HDIM, HID, 0);  // 3 <- profiled slot

  // ---- main: RoPE table, side waits on it for ropeQ ----
  rope_tab_kernel<<<(L * 64 + 255) / 256, 256>>>(tab);  // 4
  cudaEventRecord(g_ctx.e2, 0);
  cudaStreamWaitEvent(g_ctx.side, g_ctx.e2, 0);
  const int totQ = B * L * NH * 64;
  rope_f16_kernel<<<(totQ + 255) / 256, 256, 0, g_ctx.side>>>(Qp, tab, qf, NH,
                                                              totQ);  // 5
  cudaEventRecord(g_ctx.e1, g_ctx.side);

  // ---- main stream: C -> K/V chain ----
  tsplit_f16_kernel<<<dim3((NKV * HDIM) / 32, LAT / 32), 256>>>(
      Wk, wkvf, LAT, NKV * HDIM);  // rows 0..511
  tsplit_f16_kernel<<<dim3((NKV * HDIM) / 32, LAT / 32), 256>>>(
      Wv, wkvf + (size_t)NKV * HDIM * LAT, LAT, NKV * HDIM);  // rows 512..1023
  mma_gemm_f16<<<dim3(LAT / BN, M / BM), 256, GSMEM_F16>>>(
      xf, wcf, nullptr, cf, M, LAT, HID, 1);
  mma_gemm_f16<<<dim3((2 * NKV * HDIM) / BN, M / BM), 256, GSMEM_F16>>>(
      cf, wkvf, Kp, vf, M, 2 * NKV * HDIM, LAT, 2);
  const int totK = B * L * NKV * 64;
  rope_f16_kernel<<<(totK + 255) / 256, 256>>>(Kp, tab, kf, NKV, totK);
  tsplit_f16_kernel<<<dim3(HID / 32, (NH * HDIM) / 32), 256>>>(
      Wo, wof, NH * HDIM, HID);

  // ---- join, attention, output projection ----
  cudaStreamWaitEvent(0, g_ctx.e1, 0);
  attn_mma<<<dim3(NQT / 2, NH, B), 256, ASMEM>>>(qf, kf, vf, mask, yf);
  mma_gemm_f16<<<dim3(HID / BN, M / BM), 256, GSMEM_F16>>>(
      yf, wof, out, nullptr, M, HID, HID, 0);
}

// round 10
// speedup vs baseline: 11.1544x; 1.0254x over previous
#include <cuda_runtime.h>
#include <cuda_fp16.h>
#include <cstdint>
#include <math.h>

#define B 2
#define L 2048
#define HID 2048
#define NH 16
#define NKV 4
#define HDIM 128
#define LAT 512
#define SCALE 0.08838834764831845f /* 1/sqrt(128) */

// ======================= helpers =======================
__device__ __forceinline__ uint32_t smem_to_u32(const void* p) {
  uint32_t a;
  asm("{ .reg .u64 t; cvta.to.shared.u64 t, %1; cvt.u32.u64 %0, t; }"
      : "=r"(a) : "l"(p));
  return a;
}
__device__ __forceinline__ void cp16(uint32_t dst, const void* src) {
  asm volatile("cp.async.cg.shared.global [%0], [%1], 16;" ::"r"(dst), "l"(src));
}
#define CP_COMMIT() asm volatile("cp.async.commit_group;" ::: "memory")
#define CP_WAIT1() asm volatile("cp.async.wait_group 1;" ::: "memory")
#define CP_WAIT0() asm volatile("cp.async.wait_group 0;" ::: "memory")

__device__ __forceinline__ void ldsm4(uint32_t addr, uint32_t* r) {
  asm volatile("ldmatrix.sync.aligned.m8n8.x4.shared.b16 {%0,%1,%2,%3}, [%4];"
               : "=r"(r[0]), "=r"(r[1]), "=r"(r[2]), "=r"(r[3]) : "r"(addr));
}
__device__ __forceinline__ void ldsm4t(uint32_t addr, uint32_t* r) {
  asm volatile(
      "ldmatrix.sync.aligned.m8n8.x4.trans.shared.b16 {%0,%1,%2,%3}, [%4];"
      : "=r"(r[0]), "=r"(r[1]), "=r"(r[2]), "=r"(r[3]) : "r"(addr));
}
__device__ __forceinline__ void mma16816h(float* c, const uint32_t* a,
                                          const uint32_t* b) {
  asm volatile(
      "mma.sync.aligned.m16n8k16.row.col.f32.f16.f16.f32 "
      "{%0,%1,%2,%3}, {%4,%5,%6,%7}, {%8,%9}, {%0,%1,%2,%3};"
      : "+f"(c[0]), "+f"(c[1]), "+f"(c[2]), "+f"(c[3])
      : "r"(a[0]), "r"(a[1]), "r"(a[2]), "r"(a[3]), "r"(b[0]), "r"(b[1]));
}
__device__ __forceinline__ uint32_t pk2h(float lo, float hi) {
  __half2 h = __floats2half2_rn(lo, hi);
  return *(uint32_t*)&h;
}

// ======================= scratch =======================
__device__ float g_Q[(size_t)B * L * NH * HDIM];
__device__ float g_K[(size_t)B * L * NKV * HDIM];
__device__ float2 g_tab[(size_t)L * 64];  // RoPE cos/sin table

__device__ __half g_xf[(size_t)B * L * HID];
__device__ __half g_cf[(size_t)B * L * LAT];
__device__ __half g_Qf[(size_t)B * L * NH * HDIM];
__device__ __half g_Kf[(size_t)B * L * NKV * HDIM];
__device__ __half g_Vf[(size_t)B * L * NKV * HDIM];
__device__ __half g_Yf[(size_t)B * L * HID];
__device__ __half g_Wqt_f[(size_t)NH * HDIM * HID];
__device__ __half g_Wct_f[(size_t)LAT * HID];
__device__ __half g_Wkvt_f[(size_t)2 * NKV * HDIM * LAT];  // [Wk; Wv] rows
__device__ __half g_Wot_f[(size_t)HID * NH * HDIM];

// ======================= stream context (created pre-main) ==============
namespace {
struct Ctx {
  cudaStream_t side;
  cudaEvent_t e0, e1, e2;
  Ctx() {
    cudaStreamCreateWithFlags(&side, cudaStreamNonBlocking);
    cudaEventCreateWithFlags(&e0, cudaEventDisableTiming);
    cudaEventCreateWithFlags(&e1, cudaEventDisableTiming);
    cudaEventCreateWithFlags(&e2, cudaEventDisableTiming);
  }
};
Ctx g_ctx;
}  // namespace

// ======================= preprocessing =======================
__global__ void split_f16_kernel(const float* __restrict__ s,
                                 __half* __restrict__ f, int n4) {
  int i = blockIdx.x * blockDim.x + threadIdx.x;
  if (i >= n4) return;
  float4 v = ((const float4*)s)[i];
  ((__half2*)f)[2 * i] = __floats2half2_rn(v.x, v.y);
  ((__half2*)f)[2 * i + 1] = __floats2half2_rn(v.z, v.w);
}

// W[K,N] fp32 -> Wt[N,K] fp16
__global__ __launch_bounds__(256) void tsplit_f16_kernel(
    const float* __restrict__ W, __half* __restrict__ f, int K, int N) {
  __shared__ float t[32][33];
  const int n0 = blockIdx.x * 32, k0 = blockIdx.y * 32;
  const int tx = threadIdx.x & 31, ty = threadIdx.x >> 5;
#pragma unroll
  for (int i = 0; i < 32; i += 8)
    t[ty + i][tx] = W[(size_t)(k0 + ty + i) * N + n0 + tx];
  __syncthreads();
#pragma unroll
  for (int i = 0; i < 32; i += 8)
    f[(size_t)(n0 + ty + i) * K + k0 + tx] = __float2half(t[tx][ty + i]);
}

// RoPE table: tab[l][hf] = (cos, sin)(l * 10000^(-hf/64)), double precision
__global__ void rope_tab_kernel(float2* __restrict__ tab) {
  int i = blockIdx.x * blockDim.x + threadIdx.x;
  if (i >= L * 64) return;
  const int hf = i & 63;
  const int l = i >> 6;
  const double inv = exp(-(double)hf * 0.14391156831212788);
  const double fr = (double)l * inv;
  tab[i] = make_float2((float)cos(fr), (float)sin(fr));
}

// RoPE fp32 -> fp16 via table (optionally pre-scaled), layout [B, L, H, 128]
__global__ void rope_f16_kernel(const float* __restrict__ t,
                                const float2* __restrict__ tab,
                                __half* __restrict__ f, int H, int total,
                                float scl) {
  int i = blockIdx.x * blockDim.x + threadIdx.x;
  if (i >= total) return;
  const int hf = i & 63;
  const int h = (i >> 6) % H;
  const int bl = i / (64 * H);
  const int l = bl & (L - 1);
  const float2 cs = tab[l * 64 + hf];
  const size_t base = ((size_t)bl * H + h) * HDIM;
  const float a = t[base + hf];
  const float b2 = t[base + hf + 64];
  f[base + hf] = __float2half((a * cs.x - b2 * cs.y) * scl);
  f[base + hf + 64] = __float2half((b2 * cs.x + a * cs.y) * scl);
}

// ======================= fp16 GEMM v2: 64x64 warp tiles =======================
// C[M,N] = A[M,K] @ B[N,K]^T, fp16 in, fp32 accum. 4 warps/CTA, 3-stage.
// mode 0: fp32 out; mode 1: fp16 out; mode 2: KV split.
#define BM 128
#define BN 128
#define FBK 64
#define FTILEB 16384u
#define FSTAGEB 32768u
#define GSMEM_F16 (3 * 32768)

__global__ __launch_bounds__(128, 2) void mma_gemm_f16(
    const __half* __restrict__ A, const __half* __restrict__ Bm,
    float* __restrict__ C, __half* __restrict__ C16, int M, int N, int K,
    int mode) {
  extern __shared__ char smem[];
  const uint32_t sb = smem_to_u32(smem);
  const int tid = threadIdx.x, wid = tid >> 5, lane = tid & 31;
  const int wm = wid >> 1, wn = wid & 1;
  const int m0 = blockIdx.y * BM, n0 = blockIdx.x * BN;
  const __half* pA = A + (size_t)m0 * K;
  const __half* pB = Bm + (size_t)n0 * K;

  float acc[4][8][4];
#pragma unroll
  for (int f = 0; f < 4; f++)
#pragma unroll
    for (int n = 0; n < 8; n++)
#pragma unroll
      for (int e = 0; e < 4; e++) acc[f][n][e] = 0.f;

  auto load_stage = [&](int k0, int buf) {
    const uint32_t base = sb + buf * FSTAGEB;
#pragma unroll
    for (int i = 0; i < 8; i++) {
      const int idx = i * 128 + tid;
      const int r = idx >> 3, c = idx & 7;
      const uint32_t d = base + r * 128u + ((uint32_t)(c ^ (r & 7)) << 4);
      const size_t go = (size_t)r * K + k0 + c * 8;
      cp16(d, pA + go);
      cp16(d + FTILEB, pB + go);
    }
    CP_COMMIT();
  };

  const int S = K / FBK;
  load_stage(0, 0);
  load_stage(FBK, 1);

  const int rowa = wm * 64 + (lane & 15);
  const int rowb = wn * 64 + (lane & 7) + ((lane >> 4) << 3);

  for (int s = 0; s < S; s++) {
    const int buf = s % 3;
    if (s == S - 1) CP_WAIT0(); else CP_WAIT1();
    __syncthreads();
    if (s + 2 < S) load_stage((s + 2) * FBK, (s + 2) % 3);
    const uint32_t abase = sb + buf * FSTAGEB;
    const uint32_t bbase = abase + FTILEB;
#pragma unroll
    for (int ks = 0; ks < 4; ks++) {
      uint32_t ah[4][4], bh[4][4];
      const int ca = 2 * ks + (lane >> 4);
      const int cb = 2 * ks + ((lane >> 3) & 1);
#pragma unroll
      for (int f = 0; f < 4; f++) {
        const int rr = rowa + f * 16;
        ldsm4(abase + rr * 128u + ((uint32_t)(ca ^ (rr & 7)) << 4), ah[f]);
      }
#pragma unroll
      for (int p = 0; p < 4; p++) {
        const int rr = rowb + p * 16;
        ldsm4(bbase + rr * 128u + ((uint32_t)(cb ^ (rr & 7)) << 4), bh[p]);
      }
#pragma unroll
      for (int f = 0; f < 4; f++)
#pragma unroll
        for (int n = 0; n < 8; n++)
          mma16816h(acc[f][n], ah[f], &bh[n >> 1][(n & 1) * 2]);
    }
  }

#pragma unroll
  for (int f = 0; f < 4; f++) {
    const int row = m0 + wm * 64 + f * 16 + (lane >> 2);
#pragma unroll
    for (int n = 0; n < 8; n++) {
      const int col = n0 + wn * 64 + n * 8 + (lane & 3) * 2;
      if (mode == 0) {
        *(float2*)&C[(size_t)row * N + col] =
            make_float2(acc[f][n][0], acc[f][n][1]);
        *(float2*)&C[(size_t)(row + 8) * N + col] =
            make_float2(acc[f][n][2], acc[f][n][3]);
      } else if (mode == 1) {
        *(__half2*)&C16[(size_t)row * N + col] =
            __floats2half2_rn(acc[f][n][0], acc[f][n][1]);
        *(__half2*)&C16[(size_t)(row + 8) * N + col] =
            __floats2half2_rn(acc[f][n][2], acc[f][n][3]);
      } else {
        if (col < 512) {  // K -> fp32 (RoPE input), row stride 512
          *(float2*)&C[(size_t)row * 512 + col] =
              make_float2(acc[f][n][0], acc[f][n][1]);
          *(float2*)&C[(size_t)(row + 8) * 512 + col] =
              make_float2(acc[f][n][2], acc[f][n][3]);
        } else {  // V -> fp16, row stride 512
          const int cv = col - 512;
          *(__half2*)&C16[(size_t)row * 512 + cv] =
              __floats2half2_rn(acc[f][n][0], acc[f][n][1]);
          *(__half2*)&C16[(size_t)(row + 8) * 512 + cv] =
              __floats2half2_rn(acc[f][n][2], acc[f][n][3]);
        }
      }
    }
  }
}

// ======================= fp16 flash attention =======================
// Balanced pairing: each CTA does q-tiles (NQT-1-pair) then (pair).
// Q kept in smem; 2 CTAs/SM. SCALE pre-folded into Q.
#define AQ 128
#define NQT (L / AQ)
#define AKT 32
#define ASMEM (3 * 16384 + 32768) /* 3 KV stages + Q region = 80KB */

__global__ __launch_bounds__(256, 2) void attn_mma(
    const __half* __restrict__ Qf, const __half* __restrict__ Kf,
    const __half* __restrict__ Vf, const int* __restrict__ mask,
    __half* __restrict__ Yf) {
  extern __shared__ char smem[];
  const uint32_t sb = smem_to_u32(smem);
  const uint32_t sbQ = sb + 3 * 16384u;
  const int pair = blockIdx.x;
  const int h = blockIdx.y, b = blockIdx.z;
  const int hkv = h >> 2;
  const int tid = threadIdx.x, w = tid >> 5, lane = tid & 31;

  const __half* khg = Kf + ((size_t)(b * L) * NKV + hkv) * 128;
  const __half* vhg = Vf + ((size_t)(b * L) * NKV + hkv) * 128;
  const int* mrow = mask + b * L;

  const int rbB = (lane & 7) + ((lane >> 4) << 3);
  const int rvB = (lane & 7) + (((lane >> 3) & 1) << 3);
  const int rowa = w * 16 + (lane & 15);
  const uint32_t qrow = sbQ + (uint32_t)rowa * 256u;

  for (int half = 0; half < 2; half++) {
    const int qt = half == 0 ? (NQT - 1 - pair) : pair;  // heavy first
    const int q0 = qt * AQ;
    __syncthreads();  // prior half fully done with smem

    // ---- stage Q into persistent smem region ----
    {
      const __half* qg = Qf + ((size_t)(b * L + q0) * NH + h) * 128;
#pragma unroll
      for (int i = 0; i < 8; i++) {
        const int idx = i * 256 + tid;
        const int r = idx >> 4, c = idx & 15;
        const uint32_t d = sbQ + r * 256u + ((uint32_t)(c ^ (r & 7)) << 4);
        cp16(d, qg + (size_t)r * (NH * 128) + c * 8);
      }
      CP_COMMIT();
      CP_WAIT0();
      __syncthreads();
    }

    float o[16][4];
#pragma unroll
    for (int nf = 0; nf < 16; nf++)
#pragma unroll
      for (int e = 0; e < 4; e++) o[nf][e] = 0.f;
    float m2[2] = {-1e30f, -1e30f}, ls[2] = {0.f, 0.f};

    auto load_kv = [&](int t, int buf) {
      const int k0 = t * AKT;
      const uint32_t base = sb + buf * 16384u;
#pragma unroll
      for (int i = 0; i < 2; i++) {
        const int idx = i * 256 + tid;
        const int r = idx >> 4, c = idx & 15;
        const uint32_t d = base + r * 256u + ((uint32_t)(c ^ (r & 7)) << 4);
        const size_t go = (size_t)(k0 + r) * (NKV * 128) + c * 8;
        cp16(d, khg + go);
        cp16(d + 8192u, vhg + go);
      }
      CP_COMMIT();
    };

    const int nkt = qt * 4 + 4;
    load_kv(0, 0);
    if (nkt > 1) load_kv(1, 1);

    const int qa = q0 + w * 16 + (lane >> 2);
    const int qb = qa + 8;

    for (int kt = 0; kt < nkt; kt++) {
      const int buf = kt % 3;
      const int k0 = kt * AKT;
      if (kt >= nkt - 1) CP_WAIT0(); else CP_WAIT1();
      __syncthreads();
      if (kt + 2 < nkt) load_kv(kt + 2, (kt + 2) % 3);

      if (k0 <= q0 + w * 16 + 15) {
        const uint32_t kb = sb + buf * 16384u;
        float s[4][4];
#pragma unroll
        for (int n = 0; n < 4; n++)
#pragma unroll
          for (int e = 0; e < 4; e++) s[n][e] = 0.f;

#pragma unroll
        for (int kd = 0; kd < 8; kd++) {
          const int ca = 2 * kd + (lane >> 4);
          uint32_t qf4[4];
          ldsm4(qrow + ((uint32_t)(ca ^ (rowa & 7)) << 4), qf4);
          const int cb = 2 * kd + ((lane >> 3) & 1);
          const uint32_t b0a =
              kb + (uint32_t)rbB * 256u + ((uint32_t)(cb ^ (rbB & 7)) << 4);
          uint32_t bh0[4], bh1[4];
          ldsm4(b0a, bh0);
          ldsm4(b0a + 16u * 256u, bh1);
#pragma unroll
          for (int n = 0; n < 4; n++) {
            const uint32_t* bp =
                (n < 2) ? &bh0[(n & 1) * 2] : &bh1[(n & 1) * 2];
            mma16816h(s[n], qf4, bp);
          }
        }

        float rmax[2] = {-1e30f, -1e30f};
#pragma unroll
        for (int n = 0; n < 4; n++) {
          const int col = k0 + n * 8 + (lane & 3) * 2;
          const bool mk0 = mrow[col] > 0, mk1 = mrow[col + 1] > 0;
          s[n][0] = (mk0 && col <= qa) ? s[n][0] : -1e30f;
          s[n][1] = (mk1 && col + 1 <= qa) ? s[n][1] : -1e30f;
          s[n][2] = (mk0 && col <= qb) ? s[n][2] : -1e30f;
          s[n][3] = (mk1 && col + 1 <= qb) ? s[n][3] : -1e30f;
          rmax[0] = fmaxf(rmax[0], fmaxf(s[n][0], s[n][1]));
          rmax[1] = fmaxf(rmax[1], fmaxf(s[n][2], s[n][3]));
        }
#pragma unroll
        for (int off = 1; off <= 2; off <<= 1) {
          rmax[0] = fmaxf(rmax[0], __shfl_xor_sync(0xffffffffu, rmax[0], off));
          rmax[1] = fmaxf(rmax[1], __shfl_xor_sync(0xffffffffu, rmax[1], off));
        }
        const float mn0 = fmaxf(m2[0], rmax[0]);
        const float mn1 = fmaxf(m2[1], rmax[1]);
        const bool noup =
            __all_sync(0xffffffffu, (mn0 == m2[0]) & (mn1 == m2[1]));
        if (!noup) {
          const float al0 = __expf(m2[0] - mn0);
          const float al1 = __expf(m2[1] - mn1);
          ls[0] *= al0;
          ls[1] *= al1;
#pragma unroll
          for (int nf = 0; nf < 16; nf++) {
            o[nf][0] *= al0;
            o[nf][1] *= al0;
            o[nf][2] *= al1;
            o[nf][3] *= al1;
          }
          m2[0] = mn0;
          m2[1] = mn1;
        }
        float ps0 = 0.f, ps1 = 0.f;
#pragma unroll
        for (int n = 0; n < 4; n++) {
          s[n][0] = __expf(s[n][0] - m2[0]);
          s[n][1] = __expf(s[n][1] - m2[0]);
          s[n][2] = __expf(s[n][2] - m2[1]);
          s[n][3] = __expf(s[n][3] - m2[1]);
          ps0 += s[n][0] + s[n][1];
          ps1 += s[n][2] + s[n][3];
        }
#pragma unroll
        for (int off = 1; off <= 2; off <<= 1) {
          ps0 += __shfl_xor_sync(0xffffffffu, ps0, off);
          ps1 += __shfl_xor_sync(0xffffffffu, ps1, off);
        }
        ls[0] += ps0;
        ls[1] += ps1;

        uint32_t pa[2][4];
#pragma unroll
        for (int ks = 0; ks < 2; ks++) {
          pa[ks][0] = pk2h(s[2 * ks][0], s[2 * ks][1]);
          pa[ks][1] = pk2h(s[2 * ks][2], s[2 * ks][3]);
          pa[ks][2] = pk2h(s[2 * ks + 1][0], s[2 * ks + 1][1]);
          pa[ks][3] = pk2h(s[2 * ks + 1][2], s[2 * ks + 1][3]);
        }

        const uint32_t vb = kb + 8192u;
#pragma unroll
        for (int ks = 0; ks < 2; ks++) {
          const int rowv = 16 * ks + rvB;
#pragma unroll
          for (int j = 0; j < 8; j++) {
            const int cv = 2 * j + (lane >> 4);
            uint32_t vhf[4];
            ldsm4t(vb + (uint32_t)rowv * 256u +
                       ((uint32_t)(cv ^ (rowv & 7)) << 4),
                   vhf);
            mma16816h(o[2 * j], pa[ks], &vhf[0]);
            mma16816h(o[2 * j + 1], pa[ks], &vhf[2]);
          }
        }
      }
    }

    const float inv0 = 1.f / ls[0], inv1 = 1.f / ls[1];
    const size_t rA = (size_t)(b * L + qa) * (size_t)HID + h * 128;
    const size_t rB = rA + (size_t)8 * HID;
#pragma unroll
    for (int nf = 0; nf < 16; nf++) {
      const int d = nf * 8 + (lane & 3) * 2;
      *(__half2*)&Yf[rA + d] =
          __floats2half2_rn(o[nf][0] * inv0, o[nf][1] * inv0);
      *(__half2*)&Yf[rB + d] =
          __floats2half2_rn(o[nf][2] * inv1, o[nf][3] * inv1);
    }
  }
}

// ======================= launch =======================
extern "C" void kernel_launch(void* const* d_in, const int* in_sizes, int n_in,
                              void* d_out, int out_size) {
  const float* x = (const float*)d_in[0];
  const float* Wq = (const float*)d_in[1];
  const float* Wc = (const float*)d_in[2];
  const float* Wk = (const float*)d_in[3];
  const float* Wv = (const float*)d_in[4];
  const float* Wo = (const float*)d_in[5];
  const int* mask = (const int*)d_in[6];
  float* out = (float*)d_out;

  float *Qp, *Kp;
  float2* tab;
  cudaGetSymbolAddress((void**)&Qp, g_Q);
  cudaGetSymbolAddress((void**)&Kp, g_K);
  cudaGetSymbolAddress((void**)&tab, g_tab);
  __half *xf, *cf, *qf, *kf, *vf, *yf, *wqf, *wcf, *wkvf, *wof;
  cudaGetSymbolAddress((void**)&xf, g_xf);
  cudaGetSymbolAddress((void**)&cf, g_cf);
  cudaGetSymbolAddress((void**)&qf, g_Qf);
  cudaGetSymbolAddress((void**)&kf, g_Kf);
  cudaGetSymbolAddress((void**)&vf, g_Vf);
  cudaGetSymbolAddress((void**)&yf, g_Yf);
  cudaGetSymbolAddress((void**)&wqf, g_Wqt_f);
  cudaGetSymbolAddress((void**)&wcf, g_Wct_f);
  cudaGetSymbolAddress((void**)&wkvf, g_Wkvt_f);
  cudaGetSymbolAddress((void**)&wof, g_Wot_f);

  const int M = B * L;  // 4096

  cudaFuncSetAttribute(mma_gemm_f16, cudaFuncAttributeMaxDynamicSharedMemorySize,
                       GSMEM_F16);
  cudaFuncSetAttribute(attn_mma, cudaFuncAttributeMaxDynamicSharedMemorySize,
                       ASMEM);

  // ---- main stream: shared preprocessing ----
  split_f16_kernel<<<(M * HID / 4 + 255) / 256, 256>>>(x, xf, M * HID / 4);  // 0
  tsplit_f16_kernel<<<dim3((NH * HDIM) / 32, HID / 32), 256>>>(
      Wq, wqf, HID, NH * HDIM);                                              // 1
  tsplit_f16_kernel<<<dim3(LAT / 32, HID / 32), 256>>>(Wc, wcf, HID, LAT);   // 2

  // ---- fork: side stream does Q projection ----
  cudaEventRecord(g_ctx.e0, 0);
  cudaStreamWaitEvent(g_ctx.side, g_ctx.e0, 0);
  mma_gemm_f16<<<dim3((NH * HDIM) / BN, M / BM), 128, GSMEM_F16, g_ctx.side>>>(
      xf, wqf, Qp, nullptr, M, NH * HDIM, HID, 0);  // 3 <- profiled slot

  // ---- main: RoPE table, side waits on it for ropeQ (scale folded) ----
  rope_tab_kernel<<<(L * 64 + 255) / 256, 256>>>(tab);  // 4
  cudaEventRecord(g_ctx.e2, 0);
  cudaStreamWaitEvent(g_ctx.side, g_ctx.e2, 0);
  const int totQ = B * L * NH * 64;
  rope_f16_kernel<<<(totQ + 255) / 256, 256, 0, g_ctx.side>>>(Qp, tab, qf, NH,
                                                              totQ, SCALE);  // 5
  cudaEventRecord(g_ctx.e1, g_ctx.side);

  // ---- main stream: C -> K/V chain ----
  tsplit_f16_kernel<<<dim3((NKV * HDIM) / 32, LAT / 32), 256>>>(
      Wk, wkvf, LAT, NKV * HDIM);  // rows 0..511
  tsplit_f16_kernel<<<dim3((NKV * HDIM) / 32, LAT / 32), 256>>>(
      Wv, wkvf + (size_t)NKV * HDIM * LAT, LAT, NKV * HDIM);  // rows 512..1023
  mma_gemm_f16<<<dim3(LAT / BN, M / BM), 128, GSMEM_F16>>>(
      xf, wcf, nullptr, cf, M, LAT, HID, 1);
  mma_gemm_f16<<<dim3((2 * NKV * HDIM) / BN, M / BM), 128, GSMEM_F16>>>(
      cf, wkvf, Kp, vf, M, 2 * NKV * HDIM, LAT, 2);
  const int totK = B * L * NKV * 64;
  rope_f16_kernel<<<(totK + 255) / 256, 256>>>(Kp, tab, kf, NKV, totK, 1.0f);
  tsplit_f16_kernel<<<dim3(HID / 32, (NH * HDIM) / 32), 256>>>(
      Wo, wof, NH * HDIM, HID);

  // ---- join, attention, output projection ----
  cudaStreamWaitEvent(0, g_ctx.e1, 0);
  attn_mma<<<dim3(NQT / 2, NH, B), 256, ASMEM>>>(qf, kf, vf, mask, yf);
  mma_gemm_f16<<<dim3(HID / BN, M / BM), 128, GSMEM_F16>>>(
      yf, wof, out, nullptr, M, HID, HID, 0);
}